// round 3
// baseline (speedup 1.0000x reference)
#include <cuda_runtime.h>
#include <cstdint>

#define D 128
#define LAYERS 3
#define MAXN 100000
#define MAXG 2048
#define BR 64          // GEMM rows per block
#define BN_EPS 1e-5f

// ---------------- scratch (device globals; no runtime allocation) ------------
__device__ float    g_h[LAYERS][MAXN * D];   // post-BN layer outputs
__device__ float    g_agg[MAXN * D];         // h + sum_neighbors
__device__ float    g_m1[MAXN * D];          // hidden MLP activation
__device__ float    g_colsum[D];
__device__ float    g_colsq[D];
__device__ unsigned g_outmax[MAXG * LAYERS * D];

// ---------------- kernels ----------------------------------------------------

// agg = h_prev (copy), plus zero the BN stat accumulators
__global__ void copy_init_kernel(const float* __restrict__ x, int layer, int n4)
{
    int i = blockIdx.x * blockDim.x + threadIdx.x;
    const float* src = (layer == 0) ? x : g_h[layer - 1];
    if (i < n4) ((float4*)g_agg)[i] = ((const float4*)src)[i];
    if (i < D) { g_colsum[i] = 0.f; g_colsq[i] = 0.f; }
}

// one warp per edge: lane handles a float4 chunk of the 128-float row
__global__ void edge_scatter_kernel(const int* __restrict__ ei,
                                    const float* __restrict__ x,
                                    int layer, int nedges)
{
    int t = blockIdx.x * blockDim.x + threadIdx.x;
    int e = t >> 5;
    if (e >= nedges) return;
    int lane = t & 31;
    const float* h = (layer == 0) ? x : g_h[layer - 1];
    int src = ei[e];
    int dst = ei[nedges + e];
    float4 v = *(const float4*)(h + (size_t)src * D + lane * 4);
    float* p = g_agg + (size_t)dst * D + lane * 4;
    atomicAdd(p + 0, v.x);
    atomicAdd(p + 1, v.y);
    atomicAdd(p + 2, v.z);
    atomicAdd(p + 3, v.w);
}

// C = relu(A @ W + b); per-thread tile 4 rows x 8 cols; k vectorized by 4.
// 12 LDS.128 per 128 FFMA.
__global__ __launch_bounds__(256, 2) void gemm_relu_kernel(
    const float* __restrict__ A, const float* __restrict__ W,
    const float* __restrict__ bias, float* __restrict__ C,
    int n, int doStats)
{
    extern __shared__ float sm[];
    float* As = sm;              // [BR][128]  32KB
    float* Ws = sm + BR * D;     // [128][128] 64KB
    int t = threadIdx.x;
    int row0 = blockIdx.x * BR;

    // load W (128x128) to smem, coalesced float4
    for (int i = t; i < D * D / 4; i += 256)
        ((float4*)Ws)[i] = ((const float4*)W)[i];
    // load A tile (BRx128), coalesced float4, zero-pad OOB rows
    for (int i = t; i < BR * D / 4; i += 256) {
        int r = i >> 5, c4 = i & 31;
        int gr = row0 + r;
        float4 v = make_float4(0.f, 0.f, 0.f, 0.f);
        if (gr < n) v = ((const float4*)(A + (size_t)gr * D))[c4];
        ((float4*)(As + r * D))[c4] = v;
    }
    __syncthreads();

    int c0 = (t & 15) * 8;   // 16 col-groups of 8 columns
    int r0 = (t >> 4) * 4;   // 16 row-groups of 4 rows

    float acc[4][8];
#pragma unroll
    for (int r = 0; r < 4; r++)
#pragma unroll
        for (int c = 0; c < 8; c++) acc[r][c] = 0.f;

#pragma unroll 4
    for (int k0 = 0; k0 < D; k0 += 4) {
        float4 av[4];
#pragma unroll
        for (int r = 0; r < 4; r++)
            av[r] = *(float4*)(As + (r0 + r) * D + k0);   // broadcast per half-warp
        float4 wlo[4], whi[4];
#pragma unroll
        for (int kk = 0; kk < 4; kk++) {
            wlo[kk] = *(float4*)(Ws + (k0 + kk) * D + c0);
            whi[kk] = *(float4*)(Ws + (k0 + kk) * D + c0 + 4);
        }
#pragma unroll
        for (int r = 0; r < 4; r++) {
            float ak[4] = {av[r].x, av[r].y, av[r].z, av[r].w};
#pragma unroll
            for (int kk = 0; kk < 4; kk++) {
                float a = ak[kk];
                acc[r][0] += a * wlo[kk].x;
                acc[r][1] += a * wlo[kk].y;
                acc[r][2] += a * wlo[kk].z;
                acc[r][3] += a * wlo[kk].w;
                acc[r][4] += a * whi[kk].x;
                acc[r][5] += a * whi[kk].y;
                acc[r][6] += a * whi[kk].z;
                acc[r][7] += a * whi[kk].w;
            }
        }
    }

    float4 blo = *(const float4*)(bias + c0);
    float4 bhi = *(const float4*)(bias + c0 + 4);
    float bb[8] = {blo.x, blo.y, blo.z, blo.w, bhi.x, bhi.y, bhi.z, bhi.w};

    float s[8], q[8];
#pragma unroll
    for (int c = 0; c < 8; c++) { s[c] = 0.f; q[c] = 0.f; }

#pragma unroll
    for (int r = 0; r < 4; r++) {
        int gr = row0 + r0 + r;
        if (gr < n) {
            float o[8];
#pragma unroll
            for (int c = 0; c < 8; c++) {
                o[c] = fmaxf(acc[r][c] + bb[c], 0.f);
                s[c] += o[c];
                q[c] += o[c] * o[c];
            }
            float4 v0 = make_float4(o[0], o[1], o[2], o[3]);
            float4 v1 = make_float4(o[4], o[5], o[6], o[7]);
            *(float4*)(C + (size_t)gr * D + c0) = v0;
            *(float4*)(C + (size_t)gr * D + c0 + 4) = v1;
        }
    }
    if (doStats) {
#pragma unroll
        for (int c = 0; c < 8; c++) {
            atomicAdd(&g_colsum[c0 + c], s[c]);
            atomicAdd(&g_colsq[c0 + c], q[c]);
        }
    }
}

// in-place batchnorm on g_h[layer]
__global__ void bn_apply_kernel(int layer, const float* __restrict__ gamma,
                                const float* __restrict__ beta, int n, float invN)
{
    int i = blockIdx.x * blockDim.x + threadIdx.x;  // over n*32 float4s
    if (i >= n * (D / 4)) return;
    int c = (i & 31) * 4;
    float4 v = ((float4*)g_h[layer])[i];
    float4 mu, var, sc, bt;
    mu.x = g_colsum[c + 0] * invN; mu.y = g_colsum[c + 1] * invN;
    mu.z = g_colsum[c + 2] * invN; mu.w = g_colsum[c + 3] * invN;
    var.x = g_colsq[c + 0] * invN - mu.x * mu.x;
    var.y = g_colsq[c + 1] * invN - mu.y * mu.y;
    var.z = g_colsq[c + 2] * invN - mu.z * mu.z;
    var.w = g_colsq[c + 3] * invN - mu.w * mu.w;
    sc.x = gamma[c + 0] * rsqrtf(var.x + BN_EPS);
    sc.y = gamma[c + 1] * rsqrtf(var.y + BN_EPS);
    sc.z = gamma[c + 2] * rsqrtf(var.z + BN_EPS);
    sc.w = gamma[c + 3] * rsqrtf(var.w + BN_EPS);
    bt.x = beta[c + 0]; bt.y = beta[c + 1]; bt.z = beta[c + 2]; bt.w = beta[c + 3];
    v.x = (v.x - mu.x) * sc.x + bt.x;
    v.y = (v.y - mu.y) * sc.y + bt.y;
    v.z = (v.z - mu.z) * sc.z + bt.z;
    v.w = (v.w - mu.w) * sc.w + bt.w;
    ((float4*)g_h[layer])[i] = v;
}

__global__ void init_max_kernel(int total)
{
    int i = blockIdx.x * blockDim.x + threadIdx.x;
    if (i < total) g_outmax[i] = 0u;  // 0 encodes below every finite float
}

__device__ __forceinline__ unsigned f2ord(float v)
{
    unsigned u = __float_as_uint(v);
    return (u & 0x80000000u) ? ~u : (u | 0x80000000u);
}

__global__ void seg_max_kernel(const int* __restrict__ batch, int n)
{
    int t = blockIdx.x * blockDim.x + threadIdx.x;
    int node = t / (LAYERS * D);
    if (node >= n) return;
    int j = t - node * (LAYERS * D);
    int l = j >> 7, d = j & 127;
    float v = g_h[l][(size_t)node * D + d];
    int g = batch[node];
    atomicMax(&g_outmax[g * (LAYERS * D) + j], f2ord(v));
}

__global__ void decode_kernel(float* __restrict__ out, int total)
{
    int i = blockIdx.x * blockDim.x + threadIdx.x;
    if (i >= total) return;
    unsigned u = g_outmax[i];
    unsigned bits = (u & 0x80000000u) ? (u ^ 0x80000000u) : ~u;
    out[i] = __uint_as_float(bits);
}

// ---------------- launch -----------------------------------------------------

extern "C" void kernel_launch(void* const* d_in, const int* in_sizes, int n_in,
                              void* d_out, int out_size)
{
    const float* x     = (const float*)d_in[0];
    const int*   ei    = (const int*)d_in[1];    // int32 (JAX x64 disabled)
    const int*   batch = (const int*)d_in[2];    // int32
    const float* W1    = (const float*)d_in[3];
    const float* b1    = (const float*)d_in[4];
    const float* W2    = (const float*)d_in[5];
    const float* b2    = (const float*)d_in[6];
    const float* gamma = (const float*)d_in[7];
    const float* beta  = (const float*)d_in[8];
    float* out = (float*)d_out;

    int n  = in_sizes[0] / D;       // 100000
    int ne = in_sizes[1] / 2;       // 1600000
    float invN = 1.0f / (float)n;

    float *p_agg, *p_m1, *p_h;
    cudaGetSymbolAddress((void**)&p_agg, g_agg);
    cudaGetSymbolAddress((void**)&p_m1,  g_m1);
    cudaGetSymbolAddress((void**)&p_h,   g_h);

    int smem = (BR * D + D * D) * (int)sizeof(float);  // 96KB
    cudaFuncSetAttribute(gemm_relu_kernel,
                         cudaFuncAttributeMaxDynamicSharedMemorySize, smem);

    int n4 = n * (D / 4);
    int copyBlocks = (n4 + 255) / 256;
    int edgeBlocks = (ne * 32 + 255) / 256;
    int gemmBlocks = (n + BR - 1) / BR;

    for (int i = 0; i < LAYERS; i++) {
        copy_init_kernel<<<copyBlocks, 256>>>(x, i, n4);
        edge_scatter_kernel<<<edgeBlocks, 256>>>(ei, x, i, ne);
        gemm_relu_kernel<<<gemmBlocks, 256, smem>>>(
            p_agg, W1 + i * D * D, b1 + i * D, p_m1, n, 0);
        gemm_relu_kernel<<<gemmBlocks, 256, smem>>>(
            p_m1, W2 + i * D * D, b2 + i * D, p_h + (size_t)i * MAXN * D, n, 1);
        bn_apply_kernel<<<copyBlocks, 256>>>(i, gamma + i * D, beta + i * D, n, invN);
    }

    int totOut = out_size;  // G * 384
    init_max_kernel<<<(totOut + 255) / 256, 256>>>(totOut);
    int segThreads = n * LAYERS * D;
    seg_max_kernel<<<(segThreads + 255) / 256, 256>>>(batch, n);
    decode_kernel<<<(totOut + 255) / 256, 256>>>(out, totOut);
}

// round 4
// speedup vs baseline: 1.5824x; 1.5824x over previous
#include <cuda_runtime.h>
#include <cstdint>

#define D 128
#define LAYERS 3
#define MAXN 100000
#define MAXG 2048
#define BR 64          // GEMM rows per block
#define BN_EPS 1e-5f

// ---------------- scratch (device globals; no runtime allocation) ------------
__device__ float    g_h[LAYERS][MAXN * D];   // post-BN layer outputs
__device__ float    g_agg[MAXN * D];         // h + sum_neighbors
__device__ float    g_m1[MAXN * D];          // hidden MLP activation
__device__ float    g_colsum[D];
__device__ float    g_colsq[D];
__device__ unsigned g_outmax[MAXG * LAYERS * D];

// ---------------- kernels ----------------------------------------------------

// agg = h_prev (copy), plus zero the BN stat accumulators
__global__ void copy_init_kernel(const float* __restrict__ x, int layer, int n4)
{
    int i = blockIdx.x * blockDim.x + threadIdx.x;
    const float* src = (layer == 0) ? x : g_h[layer - 1];
    if (i < n4) ((float4*)g_agg)[i] = ((const float4*)src)[i];
    if (i < D) { g_colsum[i] = 0.f; g_colsq[i] = 0.f; }
}

// one warp per edge: lane handles a float4 chunk of the 128-float row
__global__ void edge_scatter_kernel(const int* __restrict__ ei,
                                    const float* __restrict__ x,
                                    int layer, int nedges)
{
    int t = blockIdx.x * blockDim.x + threadIdx.x;
    int e = t >> 5;
    if (e >= nedges) return;
    int lane = t & 31;
    const float* h = (layer == 0) ? x : g_h[layer - 1];
    int src = ei[e];
    int dst = ei[nedges + e];
    float4 v = *(const float4*)(h + (size_t)src * D + lane * 4);
    float* p = g_agg + (size_t)dst * D + lane * 4;
    atomicAdd(p + 0, v.x);
    atomicAdd(p + 1, v.y);
    atomicAdd(p + 2, v.z);
    atomicAdd(p + 3, v.w);
}

// C = relu(A @ W + b); thread tile = 4 rows x 8 cols (two 4-col chunks 64 apart);
// k vectorized by 4. W loads inside kk loop -> ~56 live floats, no spills.
__global__ __launch_bounds__(256) void gemm_relu_kernel(
    const float* __restrict__ A, const float* __restrict__ W,
    const float* __restrict__ bias, float* __restrict__ C,
    int n, int doStats)
{
    extern __shared__ float sm[];
    float* As = sm;              // [BR][128]  32KB
    float* Ws = sm + BR * D;     // [128][128] 64KB
    int t = threadIdx.x;
    int row0 = blockIdx.x * BR;

    // load W (128x128) to smem, coalesced float4
    for (int i = t; i < D * D / 4; i += 256)
        ((float4*)Ws)[i] = ((const float4*)W)[i];
    // load A tile (BRx128), coalesced float4, zero-pad OOB rows
    for (int i = t; i < BR * D / 4; i += 256) {
        int r = i >> 5, c4 = i & 31;
        int gr = row0 + r;
        float4 v = make_float4(0.f, 0.f, 0.f, 0.f);
        if (gr < n) v = ((const float4*)(A + (size_t)gr * D))[c4];
        ((float4*)(As + r * D))[c4] = v;
    }
    __syncthreads();

    int c0 = (t & 15) * 4;   // first col chunk; second at c0+64
    int r0 = (t >> 4) * 4;   // 16 row-groups of 4 rows

    float acc[4][8];
#pragma unroll
    for (int r = 0; r < 4; r++)
#pragma unroll
        for (int c = 0; c < 8; c++) acc[r][c] = 0.f;

#pragma unroll 2
    for (int k0 = 0; k0 < D; k0 += 4) {
        float4 av[4];
#pragma unroll
        for (int r = 0; r < 4; r++)
            av[r] = *(float4*)(As + (r0 + r) * D + k0);   // half-warp broadcast
#pragma unroll
        for (int kk = 0; kk < 4; kk++) {
            float4 w0 = *(float4*)(Ws + (k0 + kk) * D + c0);
            float4 w1 = *(float4*)(Ws + (k0 + kk) * D + c0 + 64);
#pragma unroll
            for (int r = 0; r < 4; r++) {
                float a = (kk == 0) ? av[r].x : (kk == 1) ? av[r].y
                        : (kk == 2) ? av[r].z : av[r].w;
                acc[r][0] += a * w0.x;
                acc[r][1] += a * w0.y;
                acc[r][2] += a * w0.z;
                acc[r][3] += a * w0.w;
                acc[r][4] += a * w1.x;
                acc[r][5] += a * w1.y;
                acc[r][6] += a * w1.z;
                acc[r][7] += a * w1.w;
            }
        }
    }

    float4 blo = *(const float4*)(bias + c0);
    float4 bhi = *(const float4*)(bias + c0 + 64);
    float bb[8] = {blo.x, blo.y, blo.z, blo.w, bhi.x, bhi.y, bhi.z, bhi.w};

    float s[8], q[8];
#pragma unroll
    for (int c = 0; c < 8; c++) { s[c] = 0.f; q[c] = 0.f; }

#pragma unroll
    for (int r = 0; r < 4; r++) {
        int gr = row0 + r0 + r;
        if (gr < n) {
            float o[8];
#pragma unroll
            for (int c = 0; c < 8; c++) {
                o[c] = fmaxf(acc[r][c] + bb[c], 0.f);
                s[c] += o[c];
                q[c] += o[c] * o[c];
            }
            *(float4*)(C + (size_t)gr * D + c0)      = make_float4(o[0], o[1], o[2], o[3]);
            *(float4*)(C + (size_t)gr * D + c0 + 64) = make_float4(o[4], o[5], o[6], o[7]);
        }
    }
    if (doStats) {
#pragma unroll
        for (int c = 0; c < 8; c++) {
            int col = (c < 4) ? (c0 + c) : (c0 + 60 + c);
            atomicAdd(&g_colsum[col], s[c]);
            atomicAdd(&g_colsq[col], q[c]);
        }
    }
}

// in-place batchnorm on g_h[layer]
__global__ void bn_apply_kernel(int layer, const float* __restrict__ gamma,
                                const float* __restrict__ beta, int n, float invN)
{
    int i = blockIdx.x * blockDim.x + threadIdx.x;  // over n*32 float4s
    if (i >= n * (D / 4)) return;
    int c = (i & 31) * 4;
    float4 v = ((float4*)g_h[layer])[i];
    float4 mu, var, sc, bt;
    mu.x = g_colsum[c + 0] * invN; mu.y = g_colsum[c + 1] * invN;
    mu.z = g_colsum[c + 2] * invN; mu.w = g_colsum[c + 3] * invN;
    var.x = g_colsq[c + 0] * invN - mu.x * mu.x;
    var.y = g_colsq[c + 1] * invN - mu.y * mu.y;
    var.z = g_colsq[c + 2] * invN - mu.z * mu.z;
    var.w = g_colsq[c + 3] * invN - mu.w * mu.w;
    sc.x = gamma[c + 0] * rsqrtf(var.x + BN_EPS);
    sc.y = gamma[c + 1] * rsqrtf(var.y + BN_EPS);
    sc.z = gamma[c + 2] * rsqrtf(var.z + BN_EPS);
    sc.w = gamma[c + 3] * rsqrtf(var.w + BN_EPS);
    bt.x = beta[c + 0]; bt.y = beta[c + 1]; bt.z = beta[c + 2]; bt.w = beta[c + 3];
    v.x = (v.x - mu.x) * sc.x + bt.x;
    v.y = (v.y - mu.y) * sc.y + bt.y;
    v.z = (v.z - mu.z) * sc.z + bt.z;
    v.w = (v.w - mu.w) * sc.w + bt.w;
    ((float4*)g_h[layer])[i] = v;
}

__global__ void init_max_kernel(int total)
{
    int i = blockIdx.x * blockDim.x + threadIdx.x;
    if (i < total) g_outmax[i] = 0u;  // 0 encodes below every finite float
}

__device__ __forceinline__ unsigned f2ord(float v)
{
    unsigned u = __float_as_uint(v);
    return (u & 0x80000000u) ? ~u : (u | 0x80000000u);
}

__global__ void seg_max_kernel(const int* __restrict__ batch, int n)
{
    int t = blockIdx.x * blockDim.x + threadIdx.x;
    int node = t / (LAYERS * D);
    if (node >= n) return;
    int j = t - node * (LAYERS * D);
    int l = j >> 7, d = j & 127;
    float v = g_h[l][(size_t)node * D + d];
    int g = batch[node];
    atomicMax(&g_outmax[g * (LAYERS * D) + j], f2ord(v));
}

__global__ void decode_kernel(float* __restrict__ out, int total)
{
    int i = blockIdx.x * blockDim.x + threadIdx.x;
    if (i >= total) return;
    unsigned u = g_outmax[i];
    unsigned bits = (u & 0x80000000u) ? (u ^ 0x80000000u) : ~u;
    out[i] = __uint_as_float(bits);
}

// ---------------- launch -----------------------------------------------------

extern "C" void kernel_launch(void* const* d_in, const int* in_sizes, int n_in,
                              void* d_out, int out_size)
{
    const float* x     = (const float*)d_in[0];
    const int*   ei    = (const int*)d_in[1];    // int32 (JAX x64 disabled)
    const int*   batch = (const int*)d_in[2];    // int32
    const float* W1    = (const float*)d_in[3];
    const float* b1    = (const float*)d_in[4];
    const float* W2    = (const float*)d_in[5];
    const float* b2    = (const float*)d_in[6];
    const float* gamma = (const float*)d_in[7];
    const float* beta  = (const float*)d_in[8];
    float* out = (float*)d_out;

    int n  = in_sizes[0] / D;       // 100000
    int ne = in_sizes[1] / 2;       // 1600000
    float invN = 1.0f / (float)n;

    float *p_agg, *p_m1, *p_h;
    cudaGetSymbolAddress((void**)&p_agg, g_agg);
    cudaGetSymbolAddress((void**)&p_m1,  g_m1);
    cudaGetSymbolAddress((void**)&p_h,   g_h);

    int smem = (BR * D + D * D) * (int)sizeof(float);  // 96KB
    cudaFuncSetAttribute(gemm_relu_kernel,
                         cudaFuncAttributeMaxDynamicSharedMemorySize, smem);

    int n4 = n * (D / 4);
    int copyBlocks = (n4 + 255) / 256;
    int edgeBlocks = (ne * 32 + 255) / 256;
    int gemmBlocks = (n + BR - 1) / BR;

    for (int i = 0; i < LAYERS; i++) {
        copy_init_kernel<<<copyBlocks, 256>>>(x, i, n4);
        edge_scatter_kernel<<<edgeBlocks, 256>>>(ei, x, i, ne);
        gemm_relu_kernel<<<gemmBlocks, 256, smem>>>(
            p_agg, W1 + i * D * D, b1 + i * D, p_m1, n, 0);
        gemm_relu_kernel<<<gemmBlocks, 256, smem>>>(
            p_m1, W2 + i * D * D, b2 + i * D, p_h + (size_t)i * MAXN * D, n, 1);
        bn_apply_kernel<<<copyBlocks, 256>>>(i, gamma + i * D, beta + i * D, n, invN);
    }

    int totOut = out_size;  // G * 384
    init_max_kernel<<<(totOut + 255) / 256, 256>>>(totOut);
    int segThreads = n * LAYERS * D;
    seg_max_kernel<<<(segThreads + 255) / 256, 256>>>(batch, n);
    decode_kernel<<<(totOut + 255) / 256, 256>>>(out, totOut);
}

// round 5
// speedup vs baseline: 3.4827x; 2.2009x over previous
#include <cuda_runtime.h>
#include <cstdint>

#define D 128
#define LAYERS 3
#define MAXN 100000
#define MAXG 2048
#define BR 64          // GEMM rows per tile
#define BN_EPS 1e-5f

// ---------------- scratch (device globals; no runtime allocation) ------------
__device__ float    g_h[LAYERS][MAXN * D];   // post-BN layer outputs
__device__ float    g_agg[MAXN * D];         // h + sum_neighbors
__device__ float    g_m1[MAXN * D];          // hidden MLP activation
__device__ float    g_colsum[D];
__device__ float    g_colsq[D];
__device__ unsigned g_outmax[MAXG * LAYERS * D];

// ---------------- kernels ----------------------------------------------------

__global__ void copy_init_kernel(const float* __restrict__ x, int layer, int n4)
{
    int i = blockIdx.x * blockDim.x + threadIdx.x;
    const float* src = (layer == 0) ? x : g_h[layer - 1];
    if (i < n4) ((float4*)g_agg)[i] = ((const float4*)src)[i];
    if (i < D) { g_colsum[i] = 0.f; g_colsq[i] = 0.f; }
}

// one warp per edge: lane handles a float4 chunk of the 128-float row
__global__ void edge_scatter_kernel(const int* __restrict__ ei,
                                    const float* __restrict__ x,
                                    int layer, int nedges)
{
    int t = blockIdx.x * blockDim.x + threadIdx.x;
    int e = t >> 5;
    if (e >= nedges) return;
    int lane = t & 31;
    const float* h = (layer == 0) ? x : g_h[layer - 1];
    int src = ei[e];
    int dst = ei[nedges + e];
    float4 v = *(const float4*)(h + (size_t)src * D + lane * 4);
    float* p = g_agg + (size_t)dst * D + lane * 4;
    atomicAdd(p + 0, v.x);
    atomicAdd(p + 1, v.y);
    atomicAdd(p + 2, v.z);
    atomicAdd(p + 3, v.w);
}

// Persistent GEMM: each block loads W once, grid-strides over 64-row tiles.
// Inner micro-kernel identical to the measured-best R2 version (8 rows x 4 cols).
// Next A tile prefetched into registers during compute.
__global__ __launch_bounds__(256) void gemm_relu_kernel(
    const float* __restrict__ A, const float* __restrict__ W,
    const float* __restrict__ bias, float* __restrict__ C,
    int n, int doStats, int numTiles)
{
    extern __shared__ float sm[];
    float* As = sm;              // [BR][128]  32KB
    float* Ws = sm + BR * D;     // [128][128] 64KB
    int t = threadIdx.x;

    // load W (128x128) once, coalesced float4
    for (int i = t; i < D * D / 4; i += 256)
        ((float4*)Ws)[i] = ((const float4*)W)[i];

    int cg = (t & 31) * 4;   // column base
    int rg = (t >> 5) * 8;   // row base within tile

    float4 b4 = *(const float4*)(bias + cg);

    // stats accumulated across all tiles, flushed once at the end
    float s0 = 0.f, s1 = 0.f, s2 = 0.f, s3 = 0.f;
    float q0 = 0.f, q1 = 0.f, q2 = 0.f, q3 = 0.f;

    // prefetch first tile into registers (8 float4 per thread)
    float4 pf[8];
    int tile = blockIdx.x;
    {
        int row0 = tile * BR;
#pragma unroll
        for (int j = 0; j < 8; j++) {
            int idx = t + j * 256;           // 0..2047
            int r = idx >> 5, c4 = idx & 31;
            int gr = row0 + r;
            pf[j] = make_float4(0.f, 0.f, 0.f, 0.f);
            if (tile < numTiles && gr < n)
                pf[j] = ((const float4*)(A + (size_t)gr * D))[c4];
        }
    }
    __syncthreads();   // Ws ready

    for (; tile < numTiles; tile += gridDim.x) {
        int row0 = tile * BR;

        // commit prefetched tile to smem
#pragma unroll
        for (int j = 0; j < 8; j++) {
            int idx = t + j * 256;
            ((float4*)As)[idx] = pf[j];
        }
        __syncthreads();

        // issue prefetch for the next tile (latency hidden behind compute)
        int ntile = tile + gridDim.x;
        if (ntile < numTiles) {
            int nrow0 = ntile * BR;
#pragma unroll
            for (int j = 0; j < 8; j++) {
                int idx = t + j * 256;
                int r = idx >> 5, c4 = idx & 31;
                int gr = nrow0 + r;
                pf[j] = make_float4(0.f, 0.f, 0.f, 0.f);
                if (gr < n)
                    pf[j] = ((const float4*)(A + (size_t)gr * D))[c4];
            }
        }

        float acc[8][4];
#pragma unroll
        for (int r = 0; r < 8; r++)
#pragma unroll
            for (int c = 0; c < 4; c++) acc[r][c] = 0.f;

#pragma unroll 8
        for (int k = 0; k < D; k++) {
            float4 w = *(float4*)(Ws + k * D + cg);
#pragma unroll
            for (int r = 0; r < 8; r++) {
                float a = As[(rg + r) * D + k];
                acc[r][0] += a * w.x;
                acc[r][1] += a * w.y;
                acc[r][2] += a * w.z;
                acc[r][3] += a * w.w;
            }
        }

#pragma unroll
        for (int r = 0; r < 8; r++) {
            int gr = row0 + rg + r;
            if (gr < n) {
                float4 o;
                o.x = fmaxf(acc[r][0] + b4.x, 0.f);
                o.y = fmaxf(acc[r][1] + b4.y, 0.f);
                o.z = fmaxf(acc[r][2] + b4.z, 0.f);
                o.w = fmaxf(acc[r][3] + b4.w, 0.f);
                *(float4*)(C + (size_t)gr * D + cg) = o;
                if (doStats) {
                    s0 += o.x; s1 += o.y; s2 += o.z; s3 += o.w;
                    q0 += o.x * o.x; q1 += o.y * o.y;
                    q2 += o.z * o.z; q3 += o.w * o.w;
                }
            }
        }
        __syncthreads();   // all readers done with As before next overwrite
    }

    if (doStats) {
        atomicAdd(&g_colsum[cg + 0], s0); atomicAdd(&g_colsum[cg + 1], s1);
        atomicAdd(&g_colsum[cg + 2], s2); atomicAdd(&g_colsum[cg + 3], s3);
        atomicAdd(&g_colsq[cg + 0], q0);  atomicAdd(&g_colsq[cg + 1], q1);
        atomicAdd(&g_colsq[cg + 2], q2);  atomicAdd(&g_colsq[cg + 3], q3);
    }
}

// in-place batchnorm on g_h[layer]
__global__ void bn_apply_kernel(int layer, const float* __restrict__ gamma,
                                const float* __restrict__ beta, int n, float invN)
{
    int i = blockIdx.x * blockDim.x + threadIdx.x;  // over n*32 float4s
    if (i >= n * (D / 4)) return;
    int c = (i & 31) * 4;
    float4 v = ((float4*)g_h[layer])[i];
    float4 mu, var, sc, bt;
    mu.x = g_colsum[c + 0] * invN; mu.y = g_colsum[c + 1] * invN;
    mu.z = g_colsum[c + 2] * invN; mu.w = g_colsum[c + 3] * invN;
    var.x = g_colsq[c + 0] * invN - mu.x * mu.x;
    var.y = g_colsq[c + 1] * invN - mu.y * mu.y;
    var.z = g_colsq[c + 2] * invN - mu.z * mu.z;
    var.w = g_colsq[c + 3] * invN - mu.w * mu.w;
    sc.x = gamma[c + 0] * rsqrtf(var.x + BN_EPS);
    sc.y = gamma[c + 1] * rsqrtf(var.y + BN_EPS);
    sc.z = gamma[c + 2] * rsqrtf(var.z + BN_EPS);
    sc.w = gamma[c + 3] * rsqrtf(var.w + BN_EPS);
    bt.x = beta[c + 0]; bt.y = beta[c + 1]; bt.z = beta[c + 2]; bt.w = beta[c + 3];
    v.x = (v.x - mu.x) * sc.x + bt.x;
    v.y = (v.y - mu.y) * sc.y + bt.y;
    v.z = (v.z - mu.z) * sc.z + bt.z;
    v.w = (v.w - mu.w) * sc.w + bt.w;
    ((float4*)g_h[layer])[i] = v;
}

__global__ void init_max_kernel(int total)
{
    int i = blockIdx.x * blockDim.x + threadIdx.x;
    if (i < total) g_outmax[i] = 0u;
}

__device__ __forceinline__ unsigned f2ord(float v)
{
    unsigned u = __float_as_uint(v);
    return (u & 0x80000000u) ? ~u : (u | 0x80000000u);
}

__global__ void seg_max_kernel(const int* __restrict__ batch, int n)
{
    int t = blockIdx.x * blockDim.x + threadIdx.x;
    int node = t / (LAYERS * D);
    if (node >= n) return;
    int j = t - node * (LAYERS * D);
    int l = j >> 7, d = j & 127;
    float v = g_h[l][(size_t)node * D + d];
    int g = batch[node];
    atomicMax(&g_outmax[g * (LAYERS * D) + j], f2ord(v));
}

__global__ void decode_kernel(float* __restrict__ out, int total)
{
    int i = blockIdx.x * blockDim.x + threadIdx.x;
    if (i >= total) return;
    unsigned u = g_outmax[i];
    unsigned bits = (u & 0x80000000u) ? (u ^ 0x80000000u) : ~u;
    out[i] = __uint_as_float(bits);
}

// ---------------- launch -----------------------------------------------------

extern "C" void kernel_launch(void* const* d_in, const int* in_sizes, int n_in,
                              void* d_out, int out_size)
{
    const float* x     = (const float*)d_in[0];
    const int*   ei    = (const int*)d_in[1];
    const int*   batch = (const int*)d_in[2];
    const float* W1    = (const float*)d_in[3];
    const float* b1    = (const float*)d_in[4];
    const float* W2    = (const float*)d_in[5];
    const float* b2    = (const float*)d_in[6];
    const float* gamma = (const float*)d_in[7];
    const float* beta  = (const float*)d_in[8];
    float* out = (float*)d_out;

    int n  = in_sizes[0] / D;       // 100000
    int ne = in_sizes[1] / 2;       // 1600000
    float invN = 1.0f / (float)n;

    float *p_agg, *p_m1, *p_h;
    cudaGetSymbolAddress((void**)&p_agg, g_agg);
    cudaGetSymbolAddress((void**)&p_m1,  g_m1);
    cudaGetSymbolAddress((void**)&p_h,   g_h);

    int smem = (BR * D + D * D) * (int)sizeof(float);  // 96KB
    cudaFuncSetAttribute(gemm_relu_kernel,
                         cudaFuncAttributeMaxDynamicSharedMemorySize, smem);

    int n4 = n * (D / 4);
    int copyBlocks = (n4 + 255) / 256;
    int edgeBlocks = (ne * 32 + 255) / 256;
    int numTiles = (n + BR - 1) / BR;
    int gemmGrid = 296;   // 2 blocks per SM, persistent

    for (int i = 0; i < LAYERS; i++) {
        copy_init_kernel<<<copyBlocks, 256>>>(x, i, n4);
        edge_scatter_kernel<<<edgeBlocks, 256>>>(ei, x, i, ne);
        gemm_relu_kernel<<<gemmGrid, 256, smem>>>(
            p_agg, W1 + i * D * D, b1 + i * D, p_m1, n, 0, numTiles);
        gemm_relu_kernel<<<gemmGrid, 256, smem>>>(
            p_m1, W2 + i * D * D, b2 + i * D, p_h + (size_t)i * MAXN * D, n, 1, numTiles);
        bn_apply_kernel<<<copyBlocks, 256>>>(i, gamma + i * D, beta + i * D, n, invN);
    }

    int totOut = out_size;  // G * 384
    init_max_kernel<<<(totOut + 255) / 256, 256>>>(totOut);
    int segThreads = n * LAYERS * D;
    seg_max_kernel<<<(segThreads + 255) / 256, 256>>>(batch, n);
    decode_kernel<<<(totOut + 255) / 256, 256>>>(out, totOut);
}

// round 6
// speedup vs baseline: 5.2499x; 1.5074x over previous
#include <cuda_runtime.h>
#include <cstdint>

#define D 128
#define LAYERS 3
#define MAXN 100000
#define MAXG 2048
#define BR 64          // GEMM rows per tile
#define BN_EPS 1e-5f

// ---------------- scratch (device globals; no runtime allocation) ------------
__device__ float    g_h[LAYERS][MAXN * D];   // post-BN layer outputs
__device__ float    g_agg[MAXN * D];         // h + sum_neighbors
__device__ float    g_m1[MAXN * D];          // hidden MLP activation
__device__ float    g_colsum[D];
__device__ float    g_colsq[D];
__device__ unsigned g_outmax[MAXG * LAYERS * D];

// ---------------- kernels ----------------------------------------------------

__global__ void copy_init_kernel(const float* __restrict__ x, int layer, int n4)
{
    int i = blockIdx.x * blockDim.x + threadIdx.x;
    const float* src = (layer == 0) ? x : g_h[layer - 1];
    if (i < n4) ((float4*)g_agg)[i] = ((const float4*)src)[i];
    if (i < D) { g_colsum[i] = 0.f; g_colsq[i] = 0.f; }
}

// one warp per edge: lane handles a float4 chunk; single vector RED per lane
__global__ void edge_scatter_kernel(const int* __restrict__ ei,
                                    const float* __restrict__ x,
                                    int layer, int nedges)
{
    int t = blockIdx.x * blockDim.x + threadIdx.x;
    int e = t >> 5;
    if (e >= nedges) return;
    int lane = t & 31;
    const float* h = (layer == 0) ? x : g_h[layer - 1];
    int src = ei[e];
    int dst = ei[nedges + e];
    float4 v = *(const float4*)(h + (size_t)src * D + lane * 4);
    float* p = g_agg + (size_t)dst * D + lane * 4;
    asm volatile("red.global.add.v4.f32 [%0], {%1,%2,%3,%4};"
                 :: "l"(p), "f"(v.x), "f"(v.y), "f"(v.z), "f"(v.w)
                 : "memory");
}

// Persistent GEMM (unchanged from measured-best R5 version).
__global__ __launch_bounds__(256) void gemm_relu_kernel(
    const float* __restrict__ A, const float* __restrict__ W,
    const float* __restrict__ bias, float* __restrict__ C,
    int n, int doStats, int numTiles)
{
    extern __shared__ float sm[];
    float* As = sm;              // [BR][128]  32KB
    float* Ws = sm + BR * D;     // [128][128] 64KB
    int t = threadIdx.x;

    for (int i = t; i < D * D / 4; i += 256)
        ((float4*)Ws)[i] = ((const float4*)W)[i];

    int cg = (t & 31) * 4;   // column base
    int rg = (t >> 5) * 8;   // row base within tile

    float4 b4 = *(const float4*)(bias + cg);

    float s0 = 0.f, s1 = 0.f, s2 = 0.f, s3 = 0.f;
    float q0 = 0.f, q1 = 0.f, q2 = 0.f, q3 = 0.f;

    float4 pf[8];
    int tile = blockIdx.x;
    {
        int row0 = tile * BR;
#pragma unroll
        for (int j = 0; j < 8; j++) {
            int idx = t + j * 256;
            int r = idx >> 5, c4 = idx & 31;
            int gr = row0 + r;
            pf[j] = make_float4(0.f, 0.f, 0.f, 0.f);
            if (tile < numTiles && gr < n)
                pf[j] = ((const float4*)(A + (size_t)gr * D))[c4];
        }
    }
    __syncthreads();

    for (; tile < numTiles; tile += gridDim.x) {
        int row0 = tile * BR;

#pragma unroll
        for (int j = 0; j < 8; j++) {
            int idx = t + j * 256;
            ((float4*)As)[idx] = pf[j];
        }
        __syncthreads();

        int ntile = tile + gridDim.x;
        if (ntile < numTiles) {
            int nrow0 = ntile * BR;
#pragma unroll
            for (int j = 0; j < 8; j++) {
                int idx = t + j * 256;
                int r = idx >> 5, c4 = idx & 31;
                int gr = nrow0 + r;
                pf[j] = make_float4(0.f, 0.f, 0.f, 0.f);
                if (gr < n)
                    pf[j] = ((const float4*)(A + (size_t)gr * D))[c4];
            }
        }

        float acc[8][4];
#pragma unroll
        for (int r = 0; r < 8; r++)
#pragma unroll
            for (int c = 0; c < 4; c++) acc[r][c] = 0.f;

#pragma unroll 8
        for (int k = 0; k < D; k++) {
            float4 w = *(float4*)(Ws + k * D + cg);
#pragma unroll
            for (int r = 0; r < 8; r++) {
                float a = As[(rg + r) * D + k];
                acc[r][0] += a * w.x;
                acc[r][1] += a * w.y;
                acc[r][2] += a * w.z;
                acc[r][3] += a * w.w;
            }
        }

#pragma unroll
        for (int r = 0; r < 8; r++) {
            int gr = row0 + rg + r;
            if (gr < n) {
                float4 o;
                o.x = fmaxf(acc[r][0] + b4.x, 0.f);
                o.y = fmaxf(acc[r][1] + b4.y, 0.f);
                o.z = fmaxf(acc[r][2] + b4.z, 0.f);
                o.w = fmaxf(acc[r][3] + b4.w, 0.f);
                *(float4*)(C + (size_t)gr * D + cg) = o;
                if (doStats) {
                    s0 += o.x; s1 += o.y; s2 += o.z; s3 += o.w;
                    q0 += o.x * o.x; q1 += o.y * o.y;
                    q2 += o.z * o.z; q3 += o.w * o.w;
                }
            }
        }
        __syncthreads();
    }

    if (doStats) {
        atomicAdd(&g_colsum[cg + 0], s0); atomicAdd(&g_colsum[cg + 1], s1);
        atomicAdd(&g_colsum[cg + 2], s2); atomicAdd(&g_colsum[cg + 3], s3);
        atomicAdd(&g_colsq[cg + 0], q0);  atomicAdd(&g_colsq[cg + 1], q1);
        atomicAdd(&g_colsq[cg + 2], q2);  atomicAdd(&g_colsq[cg + 3], q3);
    }
}

__device__ __forceinline__ unsigned f2ord(float v)
{
    unsigned u = __float_as_uint(v);
    return (u & 0x80000000u) ? ~u : (u | 0x80000000u);
}

// in-place batchnorm on g_h[layer], fused with segment-max contribution
__global__ void bn_apply_kernel(int layer, const float* __restrict__ gamma,
                                const float* __restrict__ beta,
                                const int* __restrict__ batch, int n, float invN)
{
    int i = blockIdx.x * blockDim.x + threadIdx.x;  // over n*32 float4s
    if (i >= n * (D / 4)) return;
    int node = i >> 5;
    int c = (i & 31) * 4;
    float4 v = ((float4*)g_h[layer])[i];
    float4 mu, var, sc, bt;
    mu.x = g_colsum[c + 0] * invN; mu.y = g_colsum[c + 1] * invN;
    mu.z = g_colsum[c + 2] * invN; mu.w = g_colsum[c + 3] * invN;
    var.x = g_colsq[c + 0] * invN - mu.x * mu.x;
    var.y = g_colsq[c + 1] * invN - mu.y * mu.y;
    var.z = g_colsq[c + 2] * invN - mu.z * mu.z;
    var.w = g_colsq[c + 3] * invN - mu.w * mu.w;
    sc.x = gamma[c + 0] * rsqrtf(var.x + BN_EPS);
    sc.y = gamma[c + 1] * rsqrtf(var.y + BN_EPS);
    sc.z = gamma[c + 2] * rsqrtf(var.z + BN_EPS);
    sc.w = gamma[c + 3] * rsqrtf(var.w + BN_EPS);
    bt.x = beta[c + 0]; bt.y = beta[c + 1]; bt.z = beta[c + 2]; bt.w = beta[c + 3];
    v.x = (v.x - mu.x) * sc.x + bt.x;
    v.y = (v.y - mu.y) * sc.y + bt.y;
    v.z = (v.z - mu.z) * sc.z + bt.z;
    v.w = (v.w - mu.w) * sc.w + bt.w;
    ((float4*)g_h[layer])[i] = v;

    // fused segment-max (ordered-uint REDs)
    int g = batch[node];
    unsigned* o = &g_outmax[g * (LAYERS * D) + layer * D + c];
    atomicMax(o + 0, f2ord(v.x));
    atomicMax(o + 1, f2ord(v.y));
    atomicMax(o + 2, f2ord(v.z));
    atomicMax(o + 3, f2ord(v.w));
}

__global__ void init_max_kernel(int total)
{
    int i = blockIdx.x * blockDim.x + threadIdx.x;
    if (i < total) g_outmax[i] = 0u;   // 0 encodes below every finite float
}

__global__ void decode_kernel(float* __restrict__ out, int total)
{
    int i = blockIdx.x * blockDim.x + threadIdx.x;
    if (i >= total) return;
    unsigned u = g_outmax[i];
    unsigned bits = (u & 0x80000000u) ? (u ^ 0x80000000u) : ~u;
    out[i] = __uint_as_float(bits);
}

// ---------------- launch -----------------------------------------------------

extern "C" void kernel_launch(void* const* d_in, const int* in_sizes, int n_in,
                              void* d_out, int out_size)
{
    const float* x     = (const float*)d_in[0];
    const int*   ei    = (const int*)d_in[1];
    const int*   batch = (const int*)d_in[2];
    const float* W1    = (const float*)d_in[3];
    const float* b1    = (const float*)d_in[4];
    const float* W2    = (const float*)d_in[5];
    const float* b2    = (const float*)d_in[6];
    const float* gamma = (const float*)d_in[7];
    const float* beta  = (const float*)d_in[8];
    float* out = (float*)d_out;

    int n  = in_sizes[0] / D;       // 100000
    int ne = in_sizes[1] / 2;       // 1600000
    float invN = 1.0f / (float)n;

    float *p_agg, *p_m1, *p_h;
    cudaGetSymbolAddress((void**)&p_agg, g_agg);
    cudaGetSymbolAddress((void**)&p_m1,  g_m1);
    cudaGetSymbolAddress((void**)&p_h,   g_h);

    int smem = (BR * D + D * D) * (int)sizeof(float);  // 96KB
    cudaFuncSetAttribute(gemm_relu_kernel,
                         cudaFuncAttributeMaxDynamicSharedMemorySize, smem);

    int n4 = n * (D / 4);
    int copyBlocks = (n4 + 255) / 256;
    int edgeBlocks = (ne * 32 + 255) / 256;
    int numTiles = (n + BR - 1) / BR;
    int gemmGrid = 296;   // 2 blocks per SM, persistent

    int totOut = out_size;  // G * 384
    init_max_kernel<<<(totOut + 255) / 256, 256>>>(totOut);

    for (int i = 0; i < LAYERS; i++) {
        copy_init_kernel<<<copyBlocks, 256>>>(x, i, n4);
        edge_scatter_kernel<<<edgeBlocks, 256>>>(ei, x, i, ne);
        gemm_relu_kernel<<<gemmGrid, 256, smem>>>(
            p_agg, W1 + i * D * D, b1 + i * D, p_m1, n, 0, numTiles);
        gemm_relu_kernel<<<gemmGrid, 256, smem>>>(
            p_m1, W2 + i * D * D, b2 + i * D, p_h + (size_t)i * MAXN * D, n, 1, numTiles);
        bn_apply_kernel<<<copyBlocks, 256>>>(i, gamma + i * D, beta + i * D,
                                             batch, n, invN);
    }

    decode_kernel<<<(totOut + 255) / 256, 256>>>(out, totOut);
}

// round 7
// speedup vs baseline: 7.3017x; 1.3908x over previous
#include <cuda_runtime.h>
#include <cuda_bf16.h>
#include <cstdint>

#define D 128
#define LAYERS 3
#define MAXN 100000
#define MAXG 2048
#define BR 64
#define PAD 136        // bf16 row stride (272B) -> conflict-free ldmatrix
#define BN_EPS 1e-5f

// ---------------- scratch ----------------------------------------------------
__device__ float    g_h[LAYERS][MAXN * D];
__device__ float    g_agg[MAXN * D];
__device__ float    g_m1[MAXN * D];
__device__ float    g_colsum[D];
__device__ float    g_colsq[D];
__device__ unsigned g_outmax[MAXG * LAYERS * D];

// ---------------- kernels ----------------------------------------------------

__global__ void copy_init_kernel(const float* __restrict__ x, int layer, int n4)
{
    int i = blockIdx.x * blockDim.x + threadIdx.x;
    const float* src = (layer == 0) ? x : g_h[layer - 1];
    if (i < n4) ((float4*)g_agg)[i] = ((const float4*)src)[i];
    if (i < D) { g_colsum[i] = 0.f; g_colsq[i] = 0.f; }
}

__global__ void edge_scatter_kernel(const int* __restrict__ ei,
                                    const float* __restrict__ x,
                                    int layer, int nedges)
{
    int t = blockIdx.x * blockDim.x + threadIdx.x;
    int e = t >> 5;
    if (e >= nedges) return;
    int lane = t & 31;
    const float* h = (layer == 0) ? x : g_h[layer - 1];
    int src = ei[e];
    int dst = ei[nedges + e];
    float4 v = *(const float4*)(h + (size_t)src * D + lane * 4);
    float* p = g_agg + (size_t)dst * D + lane * 4;
    asm volatile("red.global.add.v4.f32 [%0], {%1,%2,%3,%4};"
                 :: "l"(p), "f"(v.x), "f"(v.y), "f"(v.z), "f"(v.w)
                 : "memory");
}

// ---- bf16x3 tensor-core GEMM: C = relu(A@W + b), optional BN stats ----------
// Persistent blocks; W split hi/lo bf16 and transposed to [n][k] in smem once.
// Per warp: 32 rows x 32 cols (2 m16 row-subs x 4 n8 col-subs).
__device__ __forceinline__ void mma16816(float* d, const unsigned* a,
                                         const unsigned* b)
{
    asm volatile(
        "mma.sync.aligned.m16n8k16.row.col.f32.bf16.bf16.f32 "
        "{%0,%1,%2,%3}, {%4,%5,%6,%7}, {%8,%9}, {%0,%1,%2,%3};"
        : "+f"(d[0]), "+f"(d[1]), "+f"(d[2]), "+f"(d[3])
        : "r"(a[0]), "r"(a[1]), "r"(a[2]), "r"(a[3]), "r"(b[0]), "r"(b[1]));
}

__global__ __launch_bounds__(256) void gemm_relu_tc_kernel(
    const float* __restrict__ A, const float* __restrict__ W,
    const float* __restrict__ bias, float* __restrict__ C,
    int n, int doStats, int numTiles)
{
    extern __shared__ __nv_bfloat16 sb[];
    __nv_bfloat16* Ah = sb;                    // [64][PAD]
    __nv_bfloat16* Al = sb + BR * PAD;
    __nv_bfloat16* Wh = sb + 2 * BR * PAD;     // [128][PAD] transposed: [n][k]
    __nv_bfloat16* Wl = Wh + D * PAD;

    int t = threadIdx.x;
    int warp = t >> 5, lane = t & 31;

    // W fill (once): split + transpose
    for (int i = t; i < D * D; i += 256) {
        int k = i >> 7, nn = i & 127;
        float w = W[i];
        __nv_bfloat16 hh = __float2bfloat16(w);
        float rest = w - __bfloat162float(hh);
        Wh[nn * PAD + k] = hh;
        Wl[nn * PAD + k] = __float2bfloat16(rest);
    }

    int rowSub = (warp & 1) * 32;
    int colQ   = (warp >> 1) * 32;
    int cb     = (lane & 3) * 2;
    int quad   = lane >> 3, lrow = lane & 7;
    int l16    = lane & 15;

    float bias_r[4][2];
#pragma unroll
    for (int nn = 0; nn < 4; nn++) {
        bias_r[nn][0] = bias[colQ + nn * 8 + cb];
        bias_r[nn][1] = bias[colQ + nn * 8 + cb + 1];
    }

    float ss[8], sq[8];
#pragma unroll
    for (int i = 0; i < 8; i++) { ss[i] = 0.f; sq[i] = 0.f; }

    // ldmatrix lane addresses (fixed offsets within tile)
    int aRowOff = (quad & 1) * 8 + lrow;    // + rowSub + rs*16
    int aColOff = (quad >> 1) * 8;          // + k0
    int bRowOff = l16 & 7;                  // + colQ + nn*8
    int bColOff = (l16 >> 3) * 8;           // + k0

    __syncthreads();   // Wh/Wl ready

    for (int tile = blockIdx.x; tile < numTiles; tile += gridDim.x) {
        int row0 = tile * BR;

        // A fill: load fp32, split hi/lo, store bf16
#pragma unroll
        for (int j = 0; j < 8; j++) {
            int idx = t + j * 256;             // 0..2047 float4s
            int r = idx >> 5, c4 = (idx & 31) * 4;
            int gr = row0 + r;
            float4 v = make_float4(0.f, 0.f, 0.f, 0.f);
            if (gr < n) v = ((const float4*)(A + (size_t)gr * D))[idx & 31];
            __nv_bfloat16 h0 = __float2bfloat16(v.x);
            __nv_bfloat16 h1 = __float2bfloat16(v.y);
            __nv_bfloat16 h2 = __float2bfloat16(v.z);
            __nv_bfloat16 h3 = __float2bfloat16(v.w);
            unsigned hu01 = ((unsigned)__bfloat16_as_ushort(h1) << 16) | __bfloat16_as_ushort(h0);
            unsigned hu23 = ((unsigned)__bfloat16_as_ushort(h3) << 16) | __bfloat16_as_ushort(h2);
            __nv_bfloat16 l0 = __float2bfloat16(v.x - __bfloat162float(h0));
            __nv_bfloat16 l1 = __float2bfloat16(v.y - __bfloat162float(h1));
            __nv_bfloat16 l2 = __float2bfloat16(v.z - __bfloat162float(h2));
            __nv_bfloat16 l3 = __float2bfloat16(v.w - __bfloat162float(h3));
            unsigned lu01 = ((unsigned)__bfloat16_as_ushort(l1) << 16) | __bfloat16_as_ushort(l0);
            unsigned lu23 = ((unsigned)__bfloat16_as_ushort(l3) << 16) | __bfloat16_as_ushort(l2);
            *(uint2*)(Ah + r * PAD + c4) = make_uint2(hu01, hu23);
            *(uint2*)(Al + r * PAD + c4) = make_uint2(lu01, lu23);
        }
        __syncthreads();

        float acc[2][4][4];
#pragma unroll
        for (int rs = 0; rs < 2; rs++)
#pragma unroll
            for (int nn = 0; nn < 4; nn++)
#pragma unroll
                for (int u = 0; u < 4; u++) acc[rs][nn][u] = 0.f;

#pragma unroll
        for (int k0 = 0; k0 < D; k0 += 16) {
            unsigned ah[2][4], al[2][4];
#pragma unroll
            for (int rs = 0; rs < 2; rs++) {
                const __nv_bfloat16* pa =
                    Ah + (rowSub + rs * 16 + aRowOff) * PAD + k0 + aColOff;
                unsigned sa = (unsigned)__cvta_generic_to_shared(pa);
                asm volatile("ldmatrix.sync.aligned.m8n8.x4.shared.b16 "
                             "{%0,%1,%2,%3}, [%4];"
                             : "=r"(ah[rs][0]), "=r"(ah[rs][1]),
                               "=r"(ah[rs][2]), "=r"(ah[rs][3]) : "r"(sa));
                const __nv_bfloat16* pl =
                    Al + (rowSub + rs * 16 + aRowOff) * PAD + k0 + aColOff;
                unsigned sl = (unsigned)__cvta_generic_to_shared(pl);
                asm volatile("ldmatrix.sync.aligned.m8n8.x4.shared.b16 "
                             "{%0,%1,%2,%3}, [%4];"
                             : "=r"(al[rs][0]), "=r"(al[rs][1]),
                               "=r"(al[rs][2]), "=r"(al[rs][3]) : "r"(sl));
            }
            unsigned bh[4][2], bl[4][2];
#pragma unroll
            for (int nn = 0; nn < 4; nn++) {
                const __nv_bfloat16* pb =
                    Wh + (colQ + nn * 8 + bRowOff) * PAD + k0 + bColOff;
                unsigned sbh = (unsigned)__cvta_generic_to_shared(pb);
                asm volatile("ldmatrix.sync.aligned.m8n8.x2.shared.b16 "
                             "{%0,%1}, [%2];"
                             : "=r"(bh[nn][0]), "=r"(bh[nn][1]) : "r"(sbh));
                const __nv_bfloat16* pbl =
                    Wl + (colQ + nn * 8 + bRowOff) * PAD + k0 + bColOff;
                unsigned sbl = (unsigned)__cvta_generic_to_shared(pbl);
                asm volatile("ldmatrix.sync.aligned.m8n8.x2.shared.b16 "
                             "{%0,%1}, [%2];"
                             : "=r"(bl[nn][0]), "=r"(bl[nn][1]) : "r"(sbl));
            }
#pragma unroll
            for (int rs = 0; rs < 2; rs++)
#pragma unroll
                for (int nn = 0; nn < 4; nn++) {
                    mma16816(acc[rs][nn], ah[rs], bh[nn]);   // hi*hi
                    mma16816(acc[rs][nn], ah[rs], bl[nn]);   // hi*lo
                    mma16816(acc[rs][nn], al[rs], bh[nn]);   // lo*hi
                }
        }

        // epilogue: bias + relu + store + stats
#pragma unroll
        for (int rs = 0; rs < 2; rs++) {
            int rA = row0 + rowSub + rs * 16 + (lane >> 2);
            int rB = rA + 8;
#pragma unroll
            for (int nn = 0; nn < 4; nn++) {
                int c = colQ + nn * 8 + cb;
                if (rA < n) {
                    float o0 = fmaxf(acc[rs][nn][0] + bias_r[nn][0], 0.f);
                    float o1 = fmaxf(acc[rs][nn][1] + bias_r[nn][1], 0.f);
                    *(float2*)(C + (size_t)rA * D + c) = make_float2(o0, o1);
                    ss[nn * 2 + 0] += o0; sq[nn * 2 + 0] += o0 * o0;
                    ss[nn * 2 + 1] += o1; sq[nn * 2 + 1] += o1 * o1;
                }
                if (rB < n) {
                    float o2 = fmaxf(acc[rs][nn][2] + bias_r[nn][0], 0.f);
                    float o3 = fmaxf(acc[rs][nn][3] + bias_r[nn][1], 0.f);
                    *(float2*)(C + (size_t)rB * D + c) = make_float2(o2, o3);
                    ss[nn * 2 + 0] += o2; sq[nn * 2 + 0] += o2 * o2;
                    ss[nn * 2 + 1] += o3; sq[nn * 2 + 1] += o3 * o3;
                }
            }
        }
        __syncthreads();
    }

    if (doStats) {
#pragma unroll
        for (int i = 0; i < 8; i++) {
#pragma unroll
            for (int m = 4; m <= 16; m <<= 1) {
                ss[i] += __shfl_xor_sync(0xFFFFFFFFu, ss[i], m);
                sq[i] += __shfl_xor_sync(0xFFFFFFFFu, sq[i], m);
            }
        }
        if (lane < 4) {
#pragma unroll
            for (int nn = 0; nn < 4; nn++) {
                int c = colQ + nn * 8 + lane * 2;
                atomicAdd(&g_colsum[c + 0], ss[nn * 2 + 0]);
                atomicAdd(&g_colsum[c + 1], ss[nn * 2 + 1]);
                atomicAdd(&g_colsq[c + 0], sq[nn * 2 + 0]);
                atomicAdd(&g_colsq[c + 1], sq[nn * 2 + 1]);
            }
        }
    }
}

__device__ __forceinline__ unsigned f2ord(float v)
{
    unsigned u = __float_as_uint(v);
    return (u & 0x80000000u) ? ~u : (u | 0x80000000u);
}

// in-place batchnorm + fused segment-max
__global__ void bn_apply_kernel(int layer, const float* __restrict__ gamma,
                                const float* __restrict__ beta,
                                const int* __restrict__ batch, int n, float invN)
{
    int i = blockIdx.x * blockDim.x + threadIdx.x;
    if (i >= n * (D / 4)) return;
    int node = i >> 5;
    int c = (i & 31) * 4;
    float4 v = ((float4*)g_h[layer])[i];
    float4 mu, var, sc, bt;
    mu.x = g_colsum[c + 0] * invN; mu.y = g_colsum[c + 1] * invN;
    mu.z = g_colsum[c + 2] * invN; mu.w = g_colsum[c + 3] * invN;
    var.x = g_colsq[c + 0] * invN - mu.x * mu.x;
    var.y = g_colsq[c + 1] * invN - mu.y * mu.y;
    var.z = g_colsq[c + 2] * invN - mu.z * mu.z;
    var.w = g_colsq[c + 3] * invN - mu.w * mu.w;
    sc.x = gamma[c + 0] * rsqrtf(var.x + BN_EPS);
    sc.y = gamma[c + 1] * rsqrtf(var.y + BN_EPS);
    sc.z = gamma[c + 2] * rsqrtf(var.z + BN_EPS);
    sc.w = gamma[c + 3] * rsqrtf(var.w + BN_EPS);
    bt.x = beta[c + 0]; bt.y = beta[c + 1]; bt.z = beta[c + 2]; bt.w = beta[c + 3];
    v.x = (v.x - mu.x) * sc.x + bt.x;
    v.y = (v.y - mu.y) * sc.y + bt.y;
    v.z = (v.z - mu.z) * sc.z + bt.z;
    v.w = (v.w - mu.w) * sc.w + bt.w;
    ((float4*)g_h[layer])[i] = v;

    int g = batch[node];
    unsigned* o = &g_outmax[g * (LAYERS * D) + layer * D + c];
    atomicMax(o + 0, f2ord(v.x));
    atomicMax(o + 1, f2ord(v.y));
    atomicMax(o + 2, f2ord(v.z));
    atomicMax(o + 3, f2ord(v.w));
}

__global__ void init_max_kernel(int total)
{
    int i = blockIdx.x * blockDim.x + threadIdx.x;
    if (i < total) g_outmax[i] = 0u;
}

__global__ void decode_kernel(float* __restrict__ out, int total)
{
    int i = blockIdx.x * blockDim.x + threadIdx.x;
    if (i >= total) return;
    unsigned u = g_outmax[i];
    unsigned bits = (u & 0x80000000u) ? (u ^ 0x80000000u) : ~u;
    out[i] = __uint_as_float(bits);
}

// ---------------- launch -----------------------------------------------------

extern "C" void kernel_launch(void* const* d_in, const int* in_sizes, int n_in,
                              void* d_out, int out_size)
{
    const float* x     = (const float*)d_in[0];
    const int*   ei    = (const int*)d_in[1];
    const int*   batch = (const int*)d_in[2];
    const float* W1    = (const float*)d_in[3];
    const float* b1    = (const float*)d_in[4];
    const float* W2    = (const float*)d_in[5];
    const float* b2    = (const float*)d_in[6];
    const float* gamma = (const float*)d_in[7];
    const float* beta  = (const float*)d_in[8];
    float* out = (float*)d_out;

    int n  = in_sizes[0] / D;
    int ne = in_sizes[1] / 2;
    float invN = 1.0f / (float)n;

    float *p_agg, *p_m1, *p_h;
    cudaGetSymbolAddress((void**)&p_agg, g_agg);
    cudaGetSymbolAddress((void**)&p_m1,  g_m1);
    cudaGetSymbolAddress((void**)&p_h,   g_h);

    int smem = (2 * BR * PAD + 2 * D * PAD) * (int)sizeof(__nv_bfloat16); // 104448
    cudaFuncSetAttribute(gemm_relu_tc_kernel,
                         cudaFuncAttributeMaxDynamicSharedMemorySize, smem);

    int n4 = n * (D / 4);
    int copyBlocks = (n4 + 255) / 256;
    int edgeBlocks = (ne * 32 + 255) / 256;
    int numTiles = (n + BR - 1) / BR;
    int gemmGrid = 296;

    int totOut = out_size;
    init_max_kernel<<<(totOut + 255) / 256, 256>>>(totOut);

    for (int i = 0; i < LAYERS; i++) {
        copy_init_kernel<<<copyBlocks, 256>>>(x, i, n4);
        edge_scatter_kernel<<<edgeBlocks, 256>>>(ei, x, i, ne);
        gemm_relu_tc_kernel<<<gemmGrid, 256, smem>>>(
            p_agg, W1 + i * D * D, b1 + i * D, p_m1, n, 0, numTiles);
        gemm_relu_tc_kernel<<<gemmGrid, 256, smem>>>(
            p_m1, W2 + i * D * D, b2 + i * D, p_h + (size_t)i * MAXN * D, n, 1, numTiles);
        bn_apply_kernel<<<copyBlocks, 256>>>(i, gamma + i * D, beta + i * D,
                                             batch, n, invN);
    }

    decode_kernel<<<(totOut + 255) / 256, 256>>>(out, totOut);
}

// round 8
// speedup vs baseline: 11.1747x; 1.5304x over previous
#include <cuda_runtime.h>
#include <cuda_bf16.h>
#include <cstdint>

#define D 128
#define LAYERS 3
#define MAXN 100000
#define MAXE 1600000
#define MAXG 2048
#define BR 64
#define PAD 136        // bf16 row stride (272B) -> conflict-free ldmatrix
#define BN_EPS 1e-5f
#define CHUNK 1024

// ---------------- scratch ----------------------------------------------------
__device__ float    g_h[LAYERS][MAXN * D];
__device__ float    g_agg[MAXN * D];
__device__ float    g_m1[MAXN * D];
__device__ float    g_colsum[D];
__device__ float    g_colsq[D];
__device__ unsigned g_outmax[MAXG * LAYERS * D];
__device__ int      g_deg[MAXN];
__device__ int      g_fill[MAXN];
__device__ int      g_rowPtr[MAXN + 1];
__device__ int      g_chunkSum[(MAXN + CHUNK - 1) / CHUNK];
__device__ int      g_chunkOff[(MAXN + CHUNK - 1) / CHUNK];
__device__ int      g_csrSrc[MAXE];

// ---------------- CSR build --------------------------------------------------

__global__ void csr_zero_kernel(int n)
{
    int i = blockIdx.x * blockDim.x + threadIdx.x;
    if (i < n) { g_deg[i] = 0; g_fill[i] = 0; }
}

__global__ void csr_hist_kernel(const int* __restrict__ ei, int ne)
{
    int e = blockIdx.x * blockDim.x + threadIdx.x;
    if (e < ne) atomicAdd(&g_deg[ei[ne + e]], 1);
}

__global__ void chunk_sum_kernel(int n)   // 256 threads, one block per chunk
{
    __shared__ int sh[256];
    int base = blockIdx.x * CHUNK;
    int s = 0;
    for (int j = threadIdx.x; j < CHUNK; j += 256) {
        int i = base + j;
        s += (i < n) ? g_deg[i] : 0;
    }
    sh[threadIdx.x] = s; __syncthreads();
    for (int m = 128; m > 0; m >>= 1) {
        if (threadIdx.x < m) sh[threadIdx.x] += sh[threadIdx.x + m];
        __syncthreads();
    }
    if (threadIdx.x == 0) g_chunkSum[blockIdx.x] = sh[0];
}

__global__ void chunk_scan_kernel(int nc, int n)   // 1 block; serial (nc ~ 98)
{
    if (threadIdx.x == 0) {
        int acc = 0;
        for (int i = 0; i < nc; i++) { g_chunkOff[i] = acc; acc += g_chunkSum[i]; }
        g_rowPtr[n] = acc;
    }
}

__global__ void fill_rowptr_kernel(int n)   // 1024 threads per chunk
{
    __shared__ int sh[CHUNK];
    int t = threadIdx.x;
    int i = blockIdx.x * CHUNK + t;
    int v = (i < n) ? g_deg[i] : 0;
    sh[t] = v; __syncthreads();
    for (int off = 1; off < CHUNK; off <<= 1) {
        int x = 0;
        if (t >= off) x = sh[t - off];
        __syncthreads();
        sh[t] += x;
        __syncthreads();
    }
    if (i < n) g_rowPtr[i] = g_chunkOff[blockIdx.x] + sh[t] - v;
}

__global__ void csr_bucket_kernel(const int* __restrict__ ei, int ne)
{
    int e = blockIdx.x * blockDim.x + threadIdx.x;
    if (e >= ne) return;
    int s = ei[e], d = ei[ne + e];
    int pos = g_rowPtr[d] + atomicAdd(&g_fill[d], 1);
    g_csrSrc[pos] = s;
}

// ---------------- gather: agg[dst] = h[dst] + sum_{src in CSR[dst]} h[src] ---
__global__ void gather_kernel(const float* __restrict__ x, int layer, int n)
{
    int t = blockIdx.x * blockDim.x + threadIdx.x;
    if (blockIdx.x == 0 && threadIdx.x < D) {   // BN stat reset for this layer
        g_colsum[threadIdx.x] = 0.f;
        g_colsq[threadIdx.x] = 0.f;
    }
    int w = t >> 5;
    if (w >= n) return;
    int lane = t & 31;
    const float* h = (layer == 0) ? x : g_h[layer - 1];
    int start = g_rowPtr[w], end = g_rowPtr[w + 1];
    float4 acc = *(const float4*)(h + (size_t)w * D + lane * 4);   // self term
    for (int base = start; base < end; base += 32) {
        int idx = base + lane;
        int sv = (idx < end) ? g_csrSrc[idx] : 0;
        int cnt = min(32, end - base);
        for (int j = 0; j < cnt; j++) {
            int s = __shfl_sync(0xFFFFFFFFu, sv, j);
            float4 vv = *(const float4*)(h + (size_t)s * D + lane * 4);
            acc.x += vv.x; acc.y += vv.y; acc.z += vv.z; acc.w += vv.w;
        }
    }
    *(float4*)(g_agg + (size_t)w * D + lane * 4) = acc;
}

// ---- bf16x3 tensor-core GEMM (unchanged, measured-good) ---------------------
__device__ __forceinline__ void mma16816(float* d, const unsigned* a,
                                         const unsigned* b)
{
    asm volatile(
        "mma.sync.aligned.m16n8k16.row.col.f32.bf16.bf16.f32 "
        "{%0,%1,%2,%3}, {%4,%5,%6,%7}, {%8,%9}, {%0,%1,%2,%3};"
        : "+f"(d[0]), "+f"(d[1]), "+f"(d[2]), "+f"(d[3])
        : "r"(a[0]), "r"(a[1]), "r"(a[2]), "r"(a[3]), "r"(b[0]), "r"(b[1]));
}

__global__ __launch_bounds__(256) void gemm_relu_tc_kernel(
    const float* __restrict__ A, const float* __restrict__ W,
    const float* __restrict__ bias, float* __restrict__ C,
    int n, int doStats, int numTiles)
{
    extern __shared__ __nv_bfloat16 sb[];
    __nv_bfloat16* Ah = sb;                    // [64][PAD]
    __nv_bfloat16* Al = sb + BR * PAD;
    __nv_bfloat16* Wh = sb + 2 * BR * PAD;     // [128][PAD] transposed: [n][k]
    __nv_bfloat16* Wl = Wh + D * PAD;

    int t = threadIdx.x;
    int warp = t >> 5, lane = t & 31;

    for (int i = t; i < D * D; i += 256) {
        int k = i >> 7, nn = i & 127;
        float w = W[i];
        __nv_bfloat16 hh = __float2bfloat16(w);
        float rest = w - __bfloat162float(hh);
        Wh[nn * PAD + k] = hh;
        Wl[nn * PAD + k] = __float2bfloat16(rest);
    }

    int rowSub = (warp & 1) * 32;
    int colQ   = (warp >> 1) * 32;
    int cb     = (lane & 3) * 2;
    int quad   = lane >> 3, lrow = lane & 7;
    int l16    = lane & 15;

    float bias_r[4][2];
#pragma unroll
    for (int nn = 0; nn < 4; nn++) {
        bias_r[nn][0] = bias[colQ + nn * 8 + cb];
        bias_r[nn][1] = bias[colQ + nn * 8 + cb + 1];
    }

    float ss[8], sq[8];
#pragma unroll
    for (int i = 0; i < 8; i++) { ss[i] = 0.f; sq[i] = 0.f; }

    int aRowOff = (quad & 1) * 8 + lrow;
    int aColOff = (quad >> 1) * 8;
    int bRowOff = l16 & 7;
    int bColOff = (l16 >> 3) * 8;

    __syncthreads();

    for (int tile = blockIdx.x; tile < numTiles; tile += gridDim.x) {
        int row0 = tile * BR;

#pragma unroll
        for (int j = 0; j < 8; j++) {
            int idx = t + j * 256;
            int r = idx >> 5, c4 = (idx & 31) * 4;
            int gr = row0 + r;
            float4 v = make_float4(0.f, 0.f, 0.f, 0.f);
            if (gr < n) v = ((const float4*)(A + (size_t)gr * D))[idx & 31];
            __nv_bfloat16 h0 = __float2bfloat16(v.x);
            __nv_bfloat16 h1 = __float2bfloat16(v.y);
            __nv_bfloat16 h2 = __float2bfloat16(v.z);
            __nv_bfloat16 h3 = __float2bfloat16(v.w);
            unsigned hu01 = ((unsigned)__bfloat16_as_ushort(h1) << 16) | __bfloat16_as_ushort(h0);
            unsigned hu23 = ((unsigned)__bfloat16_as_ushort(h3) << 16) | __bfloat16_as_ushort(h2);
            __nv_bfloat16 l0 = __float2bfloat16(v.x - __bfloat162float(h0));
            __nv_bfloat16 l1 = __float2bfloat16(v.y - __bfloat162float(h1));
            __nv_bfloat16 l2 = __float2bfloat16(v.z - __bfloat162float(h2));
            __nv_bfloat16 l3 = __float2bfloat16(v.w - __bfloat162float(h3));
            unsigned lu01 = ((unsigned)__bfloat16_as_ushort(l1) << 16) | __bfloat16_as_ushort(l0);
            unsigned lu23 = ((unsigned)__bfloat16_as_ushort(l3) << 16) | __bfloat16_as_ushort(l2);
            *(uint2*)(Ah + r * PAD + c4) = make_uint2(hu01, hu23);
            *(uint2*)(Al + r * PAD + c4) = make_uint2(lu01, lu23);
        }
        __syncthreads();

        float acc[2][4][4];
#pragma unroll
        for (int rs = 0; rs < 2; rs++)
#pragma unroll
            for (int nn = 0; nn < 4; nn++)
#pragma unroll
                for (int u = 0; u < 4; u++) acc[rs][nn][u] = 0.f;

#pragma unroll
        for (int k0 = 0; k0 < D; k0 += 16) {
            unsigned ah[2][4], al[2][4];
#pragma unroll
            for (int rs = 0; rs < 2; rs++) {
                const __nv_bfloat16* pa =
                    Ah + (rowSub + rs * 16 + aRowOff) * PAD + k0 + aColOff;
                unsigned sa = (unsigned)__cvta_generic_to_shared(pa);
                asm volatile("ldmatrix.sync.aligned.m8n8.x4.shared.b16 "
                             "{%0,%1,%2,%3}, [%4];"
                             : "=r"(ah[rs][0]), "=r"(ah[rs][1]),
                               "=r"(ah[rs][2]), "=r"(ah[rs][3]) : "r"(sa));
                const __nv_bfloat16* pl =
                    Al + (rowSub + rs * 16 + aRowOff) * PAD + k0 + aColOff;
                unsigned sl = (unsigned)__cvta_generic_to_shared(pl);
                asm volatile("ldmatrix.sync.aligned.m8n8.x4.shared.b16 "
                             "{%0,%1,%2,%3}, [%4];"
                             : "=r"(al[rs][0]), "=r"(al[rs][1]),
                               "=r"(al[rs][2]), "=r"(al[rs][3]) : "r"(sl));
            }
            unsigned bh[4][2], bl[4][2];
#pragma unroll
            for (int nn = 0; nn < 4; nn++) {
                const __nv_bfloat16* pb =
                    Wh + (colQ + nn * 8 + bRowOff) * PAD + k0 + bColOff;
                unsigned sbh = (unsigned)__cvta_generic_to_shared(pb);
                asm volatile("ldmatrix.sync.aligned.m8n8.x2.shared.b16 "
                             "{%0,%1}, [%2];"
                             : "=r"(bh[nn][0]), "=r"(bh[nn][1]) : "r"(sbh));
                const __nv_bfloat16* pbl =
                    Wl + (colQ + nn * 8 + bRowOff) * PAD + k0 + bColOff;
                unsigned sbl = (unsigned)__cvta_generic_to_shared(pbl);
                asm volatile("ldmatrix.sync.aligned.m8n8.x2.shared.b16 "
                             "{%0,%1}, [%2];"
                             : "=r"(bl[nn][0]), "=r"(bl[nn][1]) : "r"(sbl));
            }
#pragma unroll
            for (int rs = 0; rs < 2; rs++)
#pragma unroll
                for (int nn = 0; nn < 4; nn++) {
                    mma16816(acc[rs][nn], ah[rs], bh[nn]);
                    mma16816(acc[rs][nn], ah[rs], bl[nn]);
                    mma16816(acc[rs][nn], al[rs], bh[nn]);
                }
        }

#pragma unroll
        for (int rs = 0; rs < 2; rs++) {
            int rA = row0 + rowSub + rs * 16 + (lane >> 2);
            int rB = rA + 8;
#pragma unroll
            for (int nn = 0; nn < 4; nn++) {
                int c = colQ + nn * 8 + cb;
                if (rA < n) {
                    float o0 = fmaxf(acc[rs][nn][0] + bias_r[nn][0], 0.f);
                    float o1 = fmaxf(acc[rs][nn][1] + bias_r[nn][1], 0.f);
                    *(float2*)(C + (size_t)rA * D + c) = make_float2(o0, o1);
                    ss[nn * 2 + 0] += o0; sq[nn * 2 + 0] += o0 * o0;
                    ss[nn * 2 + 1] += o1; sq[nn * 2 + 1] += o1 * o1;
                }
                if (rB < n) {
                    float o2 = fmaxf(acc[rs][nn][2] + bias_r[nn][0], 0.f);
                    float o3 = fmaxf(acc[rs][nn][3] + bias_r[nn][1], 0.f);
                    *(float2*)(C + (size_t)rB * D + c) = make_float2(o2, o3);
                    ss[nn * 2 + 0] += o2; sq[nn * 2 + 0] += o2 * o2;
                    ss[nn * 2 + 1] += o3; sq[nn * 2 + 1] += o3 * o3;
                }
            }
        }
        __syncthreads();
    }

    if (doStats) {
#pragma unroll
        for (int i = 0; i < 8; i++) {
#pragma unroll
            for (int m = 4; m <= 16; m <<= 1) {
                ss[i] += __shfl_xor_sync(0xFFFFFFFFu, ss[i], m);
                sq[i] += __shfl_xor_sync(0xFFFFFFFFu, sq[i], m);
            }
        }
        if (lane < 4) {
#pragma unroll
            for (int nn = 0; nn < 4; nn++) {
                int c = colQ + nn * 8 + lane * 2;
                atomicAdd(&g_colsum[c + 0], ss[nn * 2 + 0]);
                atomicAdd(&g_colsum[c + 1], ss[nn * 2 + 1]);
                atomicAdd(&g_colsq[c + 0], sq[nn * 2 + 0]);
                atomicAdd(&g_colsq[c + 1], sq[nn * 2 + 1]);
            }
        }
    }
}

__device__ __forceinline__ unsigned f2ord(float v)
{
    unsigned u = __float_as_uint(v);
    return (u & 0x80000000u) ? ~u : (u | 0x80000000u);
}

// in-place batchnorm + fused segment-max
__global__ void bn_apply_kernel(int layer, const float* __restrict__ gamma,
                                const float* __restrict__ beta,
                                const int* __restrict__ batch, int n, float invN)
{
    int i = blockIdx.x * blockDim.x + threadIdx.x;
    if (i >= n * (D / 4)) return;
    int node = i >> 5;
    int c = (i & 31) * 4;
    float4 v = ((float4*)g_h[layer])[i];
    float4 mu, var, sc, bt;
    mu.x = g_colsum[c + 0] * invN; mu.y = g_colsum[c + 1] * invN;
    mu.z = g_colsum[c + 2] * invN; mu.w = g_colsum[c + 3] * invN;
    var.x = g_colsq[c + 0] * invN - mu.x * mu.x;
    var.y = g_colsq[c + 1] * invN - mu.y * mu.y;
    var.z = g_colsq[c + 2] * invN - mu.z * mu.z;
    var.w = g_colsq[c + 3] * invN - mu.w * mu.w;
    sc.x = gamma[c + 0] * rsqrtf(var.x + BN_EPS);
    sc.y = gamma[c + 1] * rsqrtf(var.y + BN_EPS);
    sc.z = gamma[c + 2] * rsqrtf(var.z + BN_EPS);
    sc.w = gamma[c + 3] * rsqrtf(var.w + BN_EPS);
    bt.x = beta[c + 0]; bt.y = beta[c + 1]; bt.z = beta[c + 2]; bt.w = beta[c + 3];
    v.x = (v.x - mu.x) * sc.x + bt.x;
    v.y = (v.y - mu.y) * sc.y + bt.y;
    v.z = (v.z - mu.z) * sc.z + bt.z;
    v.w = (v.w - mu.w) * sc.w + bt.w;
    ((float4*)g_h[layer])[i] = v;

    int g = batch[node];
    unsigned* o = &g_outmax[g * (LAYERS * D) + layer * D + c];
    atomicMax(o + 0, f2ord(v.x));
    atomicMax(o + 1, f2ord(v.y));
    atomicMax(o + 2, f2ord(v.z));
    atomicMax(o + 3, f2ord(v.w));
}

__global__ void init_max_kernel(int total)
{
    int i = blockIdx.x * blockDim.x + threadIdx.x;
    if (i < total) g_outmax[i] = 0u;
}

__global__ void decode_kernel(float* __restrict__ out, int total)
{
    int i = blockIdx.x * blockDim.x + threadIdx.x;
    if (i >= total) return;
    unsigned u = g_outmax[i];
    unsigned bits = (u & 0x80000000u) ? (u ^ 0x80000000u) : ~u;
    out[i] = __uint_as_float(bits);
}

// ---------------- launch -----------------------------------------------------

extern "C" void kernel_launch(void* const* d_in, const int* in_sizes, int n_in,
                              void* d_out, int out_size)
{
    const float* x     = (const float*)d_in[0];
    const int*   ei    = (const int*)d_in[1];
    const int*   batch = (const int*)d_in[2];
    const float* W1    = (const float*)d_in[3];
    const float* b1    = (const float*)d_in[4];
    const float* W2    = (const float*)d_in[5];
    const float* b2    = (const float*)d_in[6];
    const float* gamma = (const float*)d_in[7];
    const float* beta  = (const float*)d_in[8];
    float* out = (float*)d_out;

    int n  = in_sizes[0] / D;
    int ne = in_sizes[1] / 2;
    float invN = 1.0f / (float)n;

    float *p_agg, *p_m1, *p_h;
    cudaGetSymbolAddress((void**)&p_agg, g_agg);
    cudaGetSymbolAddress((void**)&p_m1,  g_m1);
    cudaGetSymbolAddress((void**)&p_h,   g_h);

    int smem = (2 * BR * PAD + 2 * D * PAD) * (int)sizeof(__nv_bfloat16);
    cudaFuncSetAttribute(gemm_relu_tc_kernel,
                         cudaFuncAttributeMaxDynamicSharedMemorySize, smem);

    int numTiles = (n + BR - 1) / BR;
    int gemmGrid = 296;
    int nc = (n + CHUNK - 1) / CHUNK;

    // ---- CSR build (once per launch; reused by all 3 layers) ----
    csr_zero_kernel<<<(n + 255) / 256, 256>>>(n);
    csr_hist_kernel<<<(ne + 255) / 256, 256>>>(ei, ne);
    chunk_sum_kernel<<<nc, 256>>>(n);
    chunk_scan_kernel<<<1, 32>>>(nc, n);
    fill_rowptr_kernel<<<nc, CHUNK>>>(n);
    csr_bucket_kernel<<<(ne + 255) / 256, 256>>>(ei, ne);

    int totOut = out_size;
    init_max_kernel<<<(totOut + 255) / 256, 256>>>(totOut);

    int gatherBlocks = (n * 32 + 255) / 256;
    for (int i = 0; i < LAYERS; i++) {
        gather_kernel<<<gatherBlocks, 256>>>(x, i, n);
        gemm_relu_tc_kernel<<<gemmGrid, 256, smem>>>(
            p_agg, W1 + i * D * D, b1 + i * D, p_m1, n, 0, numTiles);
        gemm_relu_tc_kernel<<<gemmGrid, 256, smem>>>(
            p_m1, W2 + i * D * D, b2 + i * D, p_h + (size_t)i * MAXN * D, n, 1, numTiles);
        bn_apply_kernel<<<(n * 32 + 255) / 256, 256>>>(
            i, gamma + i * D, beta + i * D, batch, n, invN);
    }

    decode_kernel<<<(totOut + 255) / 256, 256>>>(out, totOut);
}

// round 9
// speedup vs baseline: 12.0354x; 1.0770x over previous
#include <cuda_runtime.h>
#include <cuda_bf16.h>
#include <cstdint>

#define D 128
#define LAYERS 3
#define MAXN 100000
#define MAXE 1600000
#define MAXG 2048
#define BR 64
#define PAD 136        // bf16 row stride (272B) -> conflict-free ldmatrix
#define BN_EPS 1e-5f
#define CHUNK 1024

// ---------------- scratch ----------------------------------------------------
__device__ float         g_h[LAYERS][MAXN * D];
__device__ __nv_bfloat16 g_aggH[MAXN * D];
__device__ __nv_bfloat16 g_aggL[MAXN * D];
__device__ __nv_bfloat16 g_m1H[MAXN * D];
__device__ __nv_bfloat16 g_m1L[MAXN * D];
__device__ float         g_colsum[D];
__device__ float         g_colsq[D];
__device__ int           g_deg[MAXN];
__device__ int           g_fill[MAXN];
__device__ int           g_rowPtr[MAXN + 1];
__device__ int           g_chunkSum[(MAXN + CHUNK - 1) / CHUNK];
__device__ int           g_chunkOff[(MAXN + CHUNK - 1) / CHUNK];
__device__ int           g_csrSrc[MAXE];
__device__ int           g_gstart[MAXG + 1];

// ---------------- CSR build --------------------------------------------------

__global__ void csr_zero_kernel(int n)
{
    int i = blockIdx.x * blockDim.x + threadIdx.x;
    if (i < n) { g_deg[i] = 0; g_fill[i] = 0; }
}

__global__ void csr_hist_kernel(const int* __restrict__ ei, int ne)
{
    int e = blockIdx.x * blockDim.x + threadIdx.x;
    if (e < ne) atomicAdd(&g_deg[ei[ne + e]], 1);
}

__global__ void chunk_sum_kernel(int n)
{
    __shared__ int sh[256];
    int base = blockIdx.x * CHUNK;
    int s = 0;
    for (int j = threadIdx.x; j < CHUNK; j += 256) {
        int i = base + j;
        s += (i < n) ? g_deg[i] : 0;
    }
    sh[threadIdx.x] = s; __syncthreads();
    for (int m = 128; m > 0; m >>= 1) {
        if (threadIdx.x < m) sh[threadIdx.x] += sh[threadIdx.x + m];
        __syncthreads();
    }
    if (threadIdx.x == 0) g_chunkSum[blockIdx.x] = sh[0];
}

__global__ void chunk_scan_kernel(int nc, int n)   // 1 block, 128 threads
{
    __shared__ int sh[128];
    int t = threadIdx.x;
    int v = (t < nc) ? g_chunkSum[t] : 0;
    sh[t] = v; __syncthreads();
    for (int off = 1; off < 128; off <<= 1) {
        int x = 0;
        if (t >= off) x = sh[t - off];
        __syncthreads();
        sh[t] += x;
        __syncthreads();
    }
    if (t < nc) g_chunkOff[t] = sh[t] - v;
    if (t == 127) g_rowPtr[n] = sh[127];
}

__global__ void fill_rowptr_kernel(int n)
{
    __shared__ int sh[CHUNK];
    int t = threadIdx.x;
    int i = blockIdx.x * CHUNK + t;
    int v = (i < n) ? g_deg[i] : 0;
    sh[t] = v; __syncthreads();
    for (int off = 1; off < CHUNK; off <<= 1) {
        int x = 0;
        if (t >= off) x = sh[t - off];
        __syncthreads();
        sh[t] += x;
        __syncthreads();
    }
    if (i < n) g_rowPtr[i] = g_chunkOff[blockIdx.x] + sh[t] - v;
}

__global__ void csr_bucket_kernel(const int* __restrict__ ei, int ne)
{
    int e = blockIdx.x * blockDim.x + threadIdx.x;
    if (e >= ne) return;
    int s = ei[e], d = ei[ne + e];
    int pos = g_rowPtr[d] + atomicAdd(&g_fill[d], 1);
    g_csrSrc[pos] = s;
}

// graph start offsets (batch is sorted)
__global__ void gstart_kernel(const int* __restrict__ batch, int n, int G)
{
    int i = blockIdx.x * blockDim.x + threadIdx.x;
    if (i >= n) return;
    int b = batch[i];
    int prev = (i == 0) ? -1 : batch[i - 1];
    for (int g = prev + 1; g <= b; g++) g_gstart[g] = i;
    if (i == n - 1)
        for (int g = b + 1; g <= G; g++) g_gstart[g] = n;
}

// ---------------- gather: bf16 hi/lo output ----------------------------------
__device__ __forceinline__ uint2 split_hi(float4 v)
{
    unsigned u0 = __bfloat16_as_ushort(__float2bfloat16(v.x));
    unsigned u1 = __bfloat16_as_ushort(__float2bfloat16(v.y));
    unsigned u2 = __bfloat16_as_ushort(__float2bfloat16(v.z));
    unsigned u3 = __bfloat16_as_ushort(__float2bfloat16(v.w));
    return make_uint2(u0 | (u1 << 16), u2 | (u3 << 16));
}
__device__ __forceinline__ uint2 split_lo(float4 v)
{
    float r0 = v.x - __bfloat162float(__float2bfloat16(v.x));
    float r1 = v.y - __bfloat162float(__float2bfloat16(v.y));
    float r2 = v.z - __bfloat162float(__float2bfloat16(v.z));
    float r3 = v.w - __bfloat162float(__float2bfloat16(v.w));
    unsigned u0 = __bfloat16_as_ushort(__float2bfloat16(r0));
    unsigned u1 = __bfloat16_as_ushort(__float2bfloat16(r1));
    unsigned u2 = __bfloat16_as_ushort(__float2bfloat16(r2));
    unsigned u3 = __bfloat16_as_ushort(__float2bfloat16(r3));
    return make_uint2(u0 | (u1 << 16), u2 | (u3 << 16));
}

__global__ void gather_kernel(const float* __restrict__ x, int layer, int n)
{
    int t = blockIdx.x * blockDim.x + threadIdx.x;
    if (blockIdx.x == 0 && threadIdx.x < D) {
        g_colsum[threadIdx.x] = 0.f;
        g_colsq[threadIdx.x] = 0.f;
    }
    int w = t >> 5;
    if (w >= n) return;
    int lane = t & 31;
    const float* h = (layer == 0) ? x : g_h[layer - 1];
    int start = g_rowPtr[w], end = g_rowPtr[w + 1];
    float4 acc = *(const float4*)(h + (size_t)w * D + lane * 4);
    for (int base = start; base < end; base += 32) {
        int idx = base + lane;
        int sv = (idx < end) ? g_csrSrc[idx] : 0;
        int cnt = min(32, end - base);
        for (int j = 0; j < cnt; j++) {
            int s = __shfl_sync(0xFFFFFFFFu, sv, j);
            float4 vv = *(const float4*)(h + (size_t)s * D + lane * 4);
            acc.x += vv.x; acc.y += vv.y; acc.z += vv.z; acc.w += vv.w;
        }
    }
    *(uint2*)(g_aggH + (size_t)w * D + lane * 4) = split_hi(acc);
    *(uint2*)(g_aggL + (size_t)w * D + lane * 4) = split_lo(acc);
}

// ---- bf16x3 tensor-core GEMM, pre-split inputs via cp.async -----------------
__device__ __forceinline__ void mma16816(float* d, const unsigned* a,
                                         const unsigned* b)
{
    asm volatile(
        "mma.sync.aligned.m16n8k16.row.col.f32.bf16.bf16.f32 "
        "{%0,%1,%2,%3}, {%4,%5,%6,%7}, {%8,%9}, {%0,%1,%2,%3};"
        : "+f"(d[0]), "+f"(d[1]), "+f"(d[2]), "+f"(d[3])
        : "r"(a[0]), "r"(a[1]), "r"(a[2]), "r"(a[3]), "r"(b[0]), "r"(b[1]));
}

__global__ __launch_bounds__(256) void gemm_relu_tc_kernel(
    const __nv_bfloat16* __restrict__ AH, const __nv_bfloat16* __restrict__ AL,
    const float* __restrict__ W, const float* __restrict__ bias,
    float* __restrict__ C,                      // fp32 out (GEMM2)
    __nv_bfloat16* __restrict__ CH,             // bf16 hi out (GEMM1)
    __nv_bfloat16* __restrict__ CL,             // bf16 lo out (GEMM1)
    int n, int doStats, int numTiles)
{
    extern __shared__ __nv_bfloat16 sb[];
    __nv_bfloat16* Ah = sb;                    // [64][PAD]
    __nv_bfloat16* Al = sb + BR * PAD;
    __nv_bfloat16* Wh = sb + 2 * BR * PAD;     // [128][PAD] transposed [n][k]
    __nv_bfloat16* Wl = Wh + D * PAD;

    int t = threadIdx.x;
    int warp = t >> 5, lane = t & 31;

    for (int i = t; i < D * D; i += 256) {
        int k = i >> 7, nn = i & 127;
        float w = W[i];
        __nv_bfloat16 hh = __float2bfloat16(w);
        float rest = w - __bfloat162float(hh);
        Wh[nn * PAD + k] = hh;
        Wl[nn * PAD + k] = __float2bfloat16(rest);
    }

    int rowSub = (warp & 1) * 32;
    int colQ   = (warp >> 1) * 32;
    int cb     = (lane & 3) * 2;
    int quad   = lane >> 3, lrow = lane & 7;
    int l16    = lane & 15;

    float bias_r[4][2];
#pragma unroll
    for (int nn = 0; nn < 4; nn++) {
        bias_r[nn][0] = bias[colQ + nn * 8 + cb];
        bias_r[nn][1] = bias[colQ + nn * 8 + cb + 1];
    }

    float ss[8], sq[8];
#pragma unroll
    for (int i = 0; i < 8; i++) { ss[i] = 0.f; sq[i] = 0.f; }

    int aRowOff = (quad & 1) * 8 + lrow;
    int aColOff = (quad >> 1) * 8;
    int bRowOff = l16 & 7;
    int bColOff = (l16 >> 3) * 8;

    __syncthreads();

    for (int tile = blockIdx.x; tile < numTiles; tile += gridDim.x) {
        int row0 = tile * BR;

        // A fill: 2048 16B chunks (hi+lo, 64 rows, 16 chunks/row) via cp.async
#pragma unroll
        for (int j = 0; j < 8; j++) {
            int idx = t + j * 256;
            int half = idx >> 10;             // 0=hi 1=lo
            int r = (idx & 1023) >> 4;
            int ck = idx & 15;
            int gr = row0 + r;
            __nv_bfloat16* dst = (half ? Al : Ah) + r * PAD + ck * 8;
            if (gr < n) {
                const __nv_bfloat16* src =
                    (half ? AL : AH) + (size_t)gr * D + ck * 8;
                unsigned du = (unsigned)__cvta_generic_to_shared(dst);
                asm volatile("cp.async.cg.shared.global [%0], [%1], 16;"
                             :: "r"(du), "l"(src));
            } else {
                *(float4*)dst = make_float4(0.f, 0.f, 0.f, 0.f);
            }
        }
        asm volatile("cp.async.commit_group;");
        asm volatile("cp.async.wait_group 0;");
        __syncthreads();

        float acc[2][4][4];
#pragma unroll
        for (int rs = 0; rs < 2; rs++)
#pragma unroll
            for (int nn = 0; nn < 4; nn++)
#pragma unroll
                for (int u = 0; u < 4; u++) acc[rs][nn][u] = 0.f;

#pragma unroll
        for (int k0 = 0; k0 < D; k0 += 16) {
            unsigned ah[2][4], al[2][4];
#pragma unroll
            for (int rs = 0; rs < 2; rs++) {
                const __nv_bfloat16* pa =
                    Ah + (rowSub + rs * 16 + aRowOff) * PAD + k0 + aColOff;
                unsigned sa = (unsigned)__cvta_generic_to_shared(pa);
                asm volatile("ldmatrix.sync.aligned.m8n8.x4.shared.b16 "
                             "{%0,%1,%2,%3}, [%4];"
                             : "=r"(ah[rs][0]), "=r"(ah[rs][1]),
                               "=r"(ah[rs][2]), "=r"(ah[rs][3]) : "r"(sa));
                const __nv_bfloat16* pl =
                    Al + (rowSub + rs * 16 + aRowOff) * PAD + k0 + aColOff;
                unsigned sl = (unsigned)__cvta_generic_to_shared(pl);
                asm volatile("ldmatrix.sync.aligned.m8n8.x4.shared.b16 "
                             "{%0,%1,%2,%3}, [%4];"
                             : "=r"(al[rs][0]), "=r"(al[rs][1]),
                               "=r"(al[rs][2]), "=r"(al[rs][3]) : "r"(sl));
            }
            unsigned bh[4][2], bl[4][2];
#pragma unroll
            for (int nn = 0; nn < 4; nn++) {
                const __nv_bfloat16* pb =
                    Wh + (colQ + nn * 8 + bRowOff) * PAD + k0 + bColOff;
                unsigned sbh = (unsigned)__cvta_generic_to_shared(pb);
                asm volatile("ldmatrix.sync.aligned.m8n8.x2.shared.b16 "
                             "{%0,%1}, [%2];"
                             : "=r"(bh[nn][0]), "=r"(bh[nn][1]) : "r"(sbh));
                const __nv_bfloat16* pbl =
                    Wl + (colQ + nn * 8 + bRowOff) * PAD + k0 + bColOff;
                unsigned sbl = (unsigned)__cvta_generic_to_shared(pbl);
                asm volatile("ldmatrix.sync.aligned.m8n8.x2.shared.b16 "
                             "{%0,%1}, [%2];"
                             : "=r"(bl[nn][0]), "=r"(bl[nn][1]) : "r"(sbl));
            }
#pragma unroll
            for (int rs = 0; rs < 2; rs++)
#pragma unroll
                for (int nn = 0; nn < 4; nn++) {
                    mma16816(acc[rs][nn], ah[rs], bh[nn]);
                    mma16816(acc[rs][nn], ah[rs], bl[nn]);
                    mma16816(acc[rs][nn], al[rs], bh[nn]);
                }
        }

        // epilogue
#pragma unroll
        for (int rs = 0; rs < 2; rs++) {
            int rA = row0 + rowSub + rs * 16 + (lane >> 2);
            int rB = rA + 8;
#pragma unroll
            for (int nn = 0; nn < 4; nn++) {
                int c = colQ + nn * 8 + cb;
#pragma unroll
                for (int hb = 0; hb < 2; hb++) {
                    int rr = hb ? rB : rA;
                    if (rr >= n) continue;
                    float o0 = fmaxf(acc[rs][nn][hb * 2 + 0] + bias_r[nn][0], 0.f);
                    float o1 = fmaxf(acc[rs][nn][hb * 2 + 1] + bias_r[nn][1], 0.f);
                    if (C) {
                        *(float2*)(C + (size_t)rr * D + c) = make_float2(o0, o1);
                    } else {
                        __nv_bfloat16 h0 = __float2bfloat16(o0);
                        __nv_bfloat16 h1 = __float2bfloat16(o1);
                        unsigned hp = __bfloat16_as_ushort(h0) |
                                      ((unsigned)__bfloat16_as_ushort(h1) << 16);
                        float r0f = o0 - __bfloat162float(h0);
                        float r1f = o1 - __bfloat162float(h1);
                        unsigned lp = __bfloat16_as_ushort(__float2bfloat16(r0f)) |
                                      ((unsigned)__bfloat16_as_ushort(__float2bfloat16(r1f)) << 16);
                        *(unsigned*)(CH + (size_t)rr * D + c) = hp;
                        *(unsigned*)(CL + (size_t)rr * D + c) = lp;
                    }
                    if (doStats) {
                        ss[nn * 2 + 0] += o0; sq[nn * 2 + 0] += o0 * o0;
                        ss[nn * 2 + 1] += o1; sq[nn * 2 + 1] += o1 * o1;
                    }
                }
            }
        }
        __syncthreads();
    }

    if (doStats) {
#pragma unroll
        for (int i = 0; i < 8; i++) {
#pragma unroll
            for (int m = 4; m <= 16; m <<= 1) {
                ss[i] += __shfl_xor_sync(0xFFFFFFFFu, ss[i], m);
                sq[i] += __shfl_xor_sync(0xFFFFFFFFu, sq[i], m);
            }
        }
        if (lane < 4) {
#pragma unroll
            for (int nn = 0; nn < 4; nn++) {
                int c = colQ + nn * 8 + lane * 2;
                atomicAdd(&g_colsum[c + 0], ss[nn * 2 + 0]);
                atomicAdd(&g_colsum[c + 1], ss[nn * 2 + 1]);
                atomicAdd(&g_colsq[c + 0], sq[nn * 2 + 0]);
                atomicAdd(&g_colsq[c + 1], sq[nn * 2 + 1]);
            }
        }
    }
}

// in-place batchnorm (no atomics)
__global__ void bn_apply_kernel(int layer, const float* __restrict__ gamma,
                                const float* __restrict__ beta, int n, float invN)
{
    int i = blockIdx.x * blockDim.x + threadIdx.x;
    if (i >= n * (D / 4)) return;
    int c = (i & 31) * 4;
    float4 v = ((float4*)g_h[layer])[i];
    float4 mu, var, sc, bt;
    mu.x = g_colsum[c + 0] * invN; mu.y = g_colsum[c + 1] * invN;
    mu.z = g_colsum[c + 2] * invN; mu.w = g_colsum[c + 3] * invN;
    var.x = g_colsq[c + 0] * invN - mu.x * mu.x;
    var.y = g_colsq[c + 1] * invN - mu.y * mu.y;
    var.z = g_colsq[c + 2] * invN - mu.z * mu.z;
    var.w = g_colsq[c + 3] * invN - mu.w * mu.w;
    sc.x = gamma[c + 0] * rsqrtf(var.x + BN_EPS);
    sc.y = gamma[c + 1] * rsqrtf(var.y + BN_EPS);
    sc.z = gamma[c + 2] * rsqrtf(var.z + BN_EPS);
    sc.w = gamma[c + 3] * rsqrtf(var.w + BN_EPS);
    bt.x = beta[c + 0]; bt.y = beta[c + 1]; bt.z = beta[c + 2]; bt.w = beta[c + 3];
    v.x = (v.x - mu.x) * sc.x + bt.x;
    v.y = (v.y - mu.y) * sc.y + bt.y;
    v.z = (v.z - mu.z) * sc.z + bt.z;
    v.w = (v.w - mu.w) * sc.w + bt.w;
    ((float4*)g_h[layer])[i] = v;
}

// one block per graph; batch sorted -> contiguous node ranges; no atomics
__global__ void seg_max_kernel(float* __restrict__ out, int n)
{
    int g = blockIdx.x;
    int col = threadIdx.x;      // 0..127
    int s = g_gstart[g], e = g_gstart[g + 1];
    float m0 = -3.402823466e+38f, m1 = m0, m2 = m0;
    for (int node = s; node < e; node++) {
        m0 = fmaxf(m0, g_h[0][(size_t)node * D + col]);
        m1 = fmaxf(m1, g_h[1][(size_t)node * D + col]);
        m2 = fmaxf(m2, g_h[2][(size_t)node * D + col]);
    }
    out[g * (LAYERS * D) + col] = m0;
    out[g * (LAYERS * D) + D + col] = m1;
    out[g * (LAYERS * D) + 2 * D + col] = m2;
}

// ---------------- launch -----------------------------------------------------

extern "C" void kernel_launch(void* const* d_in, const int* in_sizes, int n_in,
                              void* d_out, int out_size)
{
    const float* x     = (const float*)d_in[0];
    const int*   ei    = (const int*)d_in[1];
    const int*   batch = (const int*)d_in[2];
    const float* W1    = (const float*)d_in[3];
    const float* b1    = (const float*)d_in[4];
    const float* W2    = (const float*)d_in[5];
    const float* b2    = (const float*)d_in[6];
    const float* gamma = (const float*)d_in[7];
    const float* beta  = (const float*)d_in[8];
    float* out = (float*)d_out;

    int n  = in_sizes[0] / D;
    int ne = in_sizes[1] / 2;
    int G  = out_size / (LAYERS * D);
    float invN = 1.0f / (float)n;

    __nv_bfloat16 *p_aggH, *p_aggL, *p_m1H, *p_m1L;
    float *p_h;
    cudaGetSymbolAddress((void**)&p_aggH, g_aggH);
    cudaGetSymbolAddress((void**)&p_aggL, g_aggL);
    cudaGetSymbolAddress((void**)&p_m1H,  g_m1H);
    cudaGetSymbolAddress((void**)&p_m1L,  g_m1L);
    cudaGetSymbolAddress((void**)&p_h,    g_h);

    int smem = (2 * BR * PAD + 2 * D * PAD) * (int)sizeof(__nv_bfloat16);
    cudaFuncSetAttribute(gemm_relu_tc_kernel,
                         cudaFuncAttributeMaxDynamicSharedMemorySize, smem);

    int numTiles = (n + BR - 1) / BR;
    int gemmGrid = 296;
    int nc = (n + CHUNK - 1) / CHUNK;

    // CSR build (once; reused across layers)
    csr_zero_kernel<<<(n + 255) / 256, 256>>>(n);
    csr_hist_kernel<<<(ne + 255) / 256, 256>>>(ei, ne);
    chunk_sum_kernel<<<nc, 256>>>(n);
    chunk_scan_kernel<<<1, 128>>>(nc, n);
    fill_rowptr_kernel<<<nc, CHUNK>>>(n);
    csr_bucket_kernel<<<(ne + 255) / 256, 256>>>(ei, ne);
    gstart_kernel<<<(n + 255) / 256, 256>>>(batch, n, G);

    int gatherBlocks = (n * 32 + 255) / 256;
    for (int i = 0; i < LAYERS; i++) {
        gather_kernel<<<gatherBlocks, 256>>>(x, i, n);
        gemm_relu_tc_kernel<<<gemmGrid, 256, smem>>>(
            p_aggH, p_aggL, W1 + i * D * D, b1 + i * D,
            nullptr, p_m1H, p_m1L, n, 0, numTiles);
        gemm_relu_tc_kernel<<<gemmGrid, 256, smem>>>(
            p_m1H, p_m1L, W2 + i * D * D, b2 + i * D,
            p_h + (size_t)i * MAXN * D, nullptr, nullptr, n, 1, numTiles);
        bn_apply_kernel<<<(n * 32 + 255) / 256, 256>>>(
            i, gamma + i * D, beta + i * D, n, invN);
    }

    seg_max_kernel<<<G, D>>>(out, n);
}

// round 10
// speedup vs baseline: 13.6454x; 1.1338x over previous
#include <cuda_runtime.h>
#include <cuda_bf16.h>
#include <cstdint>

#define D 128
#define LAYERS 3
#define MAXN 100000
#define MAXE 1600000
#define MAXG 2048
#define BR 64
#define PAD 136        // bf16 row stride (272B) -> conflict-free ldmatrix
#define BN_EPS 1e-5f
#define CHUNK 1024

// ---------------- scratch ----------------------------------------------------
__device__ float         g_m[LAYERS][MAXN * D];   // pre-BN layer outputs
__device__ __nv_bfloat16 g_aggH[MAXN * D];
__device__ __nv_bfloat16 g_aggL[MAXN * D];
__device__ __nv_bfloat16 g_m1H[MAXN * D];
__device__ __nv_bfloat16 g_m1L[MAXN * D];
__device__ float         g_colsum[D];
__device__ float         g_colsq[D];
__device__ float         g_bnsc[LAYERS][D];
__device__ float         g_bnbt[LAYERS][D];
__device__ int           g_deg[MAXN];
__device__ int           g_fill[MAXN];
__device__ int           g_rowPtr[MAXN + 1];
__device__ int           g_chunkSum[(MAXN + CHUNK - 1) / CHUNK];
__device__ int           g_chunkOff[(MAXN + CHUNK - 1) / CHUNK];
__device__ int           g_csrSrc[MAXE];
__device__ int           g_gstart[MAXG + 1];

// ---------------- CSR build --------------------------------------------------

__global__ void csr_zero_kernel(int n)
{
    int i = blockIdx.x * blockDim.x + threadIdx.x;
    if (i < n) { g_deg[i] = 0; g_fill[i] = 0; }
}

__global__ void csr_hist_kernel(const int* __restrict__ ei, int ne)
{
    int e = blockIdx.x * blockDim.x + threadIdx.x;
    if (e < ne) atomicAdd(&g_deg[ei[ne + e]], 1);
}

__global__ void chunk_sum_kernel(int n)
{
    __shared__ int sh[256];
    int base = blockIdx.x * CHUNK;
    int s = 0;
    for (int j = threadIdx.x; j < CHUNK; j += 256) {
        int i = base + j;
        s += (i < n) ? g_deg[i] : 0;
    }
    sh[threadIdx.x] = s; __syncthreads();
    for (int m = 128; m > 0; m >>= 1) {
        if (threadIdx.x < m) sh[threadIdx.x] += sh[threadIdx.x + m];
        __syncthreads();
    }
    if (threadIdx.x == 0) g_chunkSum[blockIdx.x] = sh[0];
}

__global__ void chunk_scan_kernel(int nc, int n)   // 1 block, 128 threads
{
    __shared__ int sh[128];
    int t = threadIdx.x;
    int v = (t < nc) ? g_chunkSum[t] : 0;
    sh[t] = v; __syncthreads();
    for (int off = 1; off < 128; off <<= 1) {
        int x = 0;
        if (t >= off) x = sh[t - off];
        __syncthreads();
        sh[t] += x;
        __syncthreads();
    }
    if (t < nc) g_chunkOff[t] = sh[t] - v;
    if (t == 127) g_rowPtr[n] = sh[127];
}

__global__ void fill_rowptr_kernel(int n)
{
    __shared__ int sh[CHUNK];
    int t = threadIdx.x;
    int i = blockIdx.x * CHUNK + t;
    int v = (i < n) ? g_deg[i] : 0;
    sh[t] = v; __syncthreads();
    for (int off = 1; off < CHUNK; off <<= 1) {
        int x = 0;
        if (t >= off) x = sh[t - off];
        __syncthreads();
        sh[t] += x;
        __syncthreads();
    }
    if (i < n) g_rowPtr[i] = g_chunkOff[blockIdx.x] + sh[t] - v;
}

__global__ void csr_bucket_kernel(const int* __restrict__ ei, int ne)
{
    int e = blockIdx.x * blockDim.x + threadIdx.x;
    if (e >= ne) return;
    int s = ei[e], d = ei[ne + e];
    int pos = g_rowPtr[d] + atomicAdd(&g_fill[d], 1);
    g_csrSrc[pos] = s;
}

// graph start offsets (batch is sorted)
__global__ void gstart_kernel(const int* __restrict__ batch, int n, int G)
{
    int i = blockIdx.x * blockDim.x + threadIdx.x;
    if (i >= n) return;
    int b = batch[i];
    int prev = (i == 0) ? -1 : batch[i - 1];
    for (int g = prev + 1; g <= b; g++) g_gstart[g] = i;
    if (i == n - 1)
        for (int g = b + 1; g <= G; g++) g_gstart[g] = n;
}

// ---------------- bf16 split helpers -----------------------------------------
__device__ __forceinline__ uint2 split_hi(float4 v)
{
    unsigned u0 = __bfloat16_as_ushort(__float2bfloat16(v.x));
    unsigned u1 = __bfloat16_as_ushort(__float2bfloat16(v.y));
    unsigned u2 = __bfloat16_as_ushort(__float2bfloat16(v.z));
    unsigned u3 = __bfloat16_as_ushort(__float2bfloat16(v.w));
    return make_uint2(u0 | (u1 << 16), u2 | (u3 << 16));
}
__device__ __forceinline__ uint2 split_lo(float4 v)
{
    float r0 = v.x - __bfloat162float(__float2bfloat16(v.x));
    float r1 = v.y - __bfloat162float(__float2bfloat16(v.y));
    float r2 = v.z - __bfloat162float(__float2bfloat16(v.z));
    float r3 = v.w - __bfloat162float(__float2bfloat16(v.w));
    unsigned u0 = __bfloat16_as_ushort(__float2bfloat16(r0));
    unsigned u1 = __bfloat16_as_ushort(__float2bfloat16(r1));
    unsigned u2 = __bfloat16_as_ushort(__float2bfloat16(r2));
    unsigned u3 = __bfloat16_as_ushort(__float2bfloat16(r3));
    return make_uint2(u0 | (u1 << 16), u2 | (u3 << 16));
}

// ---------------- gather: BN affine folded in, bf16 hi/lo out ----------------
// layer 0: input = x (no affine). layer i>0: input = g_m[i-1] with affine
//   h = sc*m + bt  =>  acc = sc*(m_self + sum m_j) + (deg+1)*bt
__global__ void gather_kernel(const float* __restrict__ x, int layer, int n)
{
    int t = blockIdx.x * blockDim.x + threadIdx.x;
    if (blockIdx.x == 0 && threadIdx.x < D) {    // reset BN stats for this layer
        g_colsum[threadIdx.x] = 0.f;
        g_colsq[threadIdx.x] = 0.f;
    }
    int w = t >> 5;
    if (w >= n) return;
    int lane = t & 31;
    const float* h = (layer == 0) ? x : g_m[layer - 1];
    int start = g_rowPtr[w], end = g_rowPtr[w + 1];
    float4 acc = *(const float4*)(h + (size_t)w * D + lane * 4);   // self (raw)
    for (int base = start; base < end; base += 32) {
        int idx = base + lane;
        int sv = (idx < end) ? g_csrSrc[idx] : 0;
        int cnt = min(32, end - base);
        for (int j = 0; j < cnt; j++) {
            int s = __shfl_sync(0xFFFFFFFFu, sv, j);
            float4 vv = *(const float4*)(h + (size_t)s * D + lane * 4);
            acc.x += vv.x; acc.y += vv.y; acc.z += vv.z; acc.w += vv.w;
        }
    }
    if (layer > 0) {
        float4 sc = *(const float4*)(&g_bnsc[layer - 1][lane * 4]);
        float4 bt = *(const float4*)(&g_bnbt[layer - 1][lane * 4]);
        float cnt1 = (float)(end - start + 1);
        acc.x = sc.x * acc.x + cnt1 * bt.x;
        acc.y = sc.y * acc.y + cnt1 * bt.y;
        acc.z = sc.z * acc.z + cnt1 * bt.z;
        acc.w = sc.w * acc.w + cnt1 * bt.w;
    }
    *(uint2*)(g_aggH + (size_t)w * D + lane * 4) = split_hi(acc);
    *(uint2*)(g_aggL + (size_t)w * D + lane * 4) = split_lo(acc);
}

// per-layer BN coefficients from accumulated stats (1 block, 128 threads)
__global__ void bn_stats_kernel(int layer, const float* __restrict__ gamma,
                                const float* __restrict__ beta, float invN)
{
    int c = threadIdx.x;
    float mean = g_colsum[c] * invN;
    float var = g_colsq[c] * invN - mean * mean;
    float sc = gamma[c] * rsqrtf(var + BN_EPS);
    g_bnsc[layer][c] = sc;
    g_bnbt[layer][c] = beta[c] - sc * mean;
}

// ---- bf16x3 tensor-core GEMM, pre-split inputs via cp.async -----------------
__device__ __forceinline__ void mma16816(float* d, const unsigned* a,
                                         const unsigned* b)
{
    asm volatile(
        "mma.sync.aligned.m16n8k16.row.col.f32.bf16.bf16.f32 "
        "{%0,%1,%2,%3}, {%4,%5,%6,%7}, {%8,%9}, {%0,%1,%2,%3};"
        : "+f"(d[0]), "+f"(d[1]), "+f"(d[2]), "+f"(d[3])
        : "r"(a[0]), "r"(a[1]), "r"(a[2]), "r"(a[3]), "r"(b[0]), "r"(b[1]));
}

__global__ __launch_bounds__(256) void gemm_relu_tc_kernel(
    const __nv_bfloat16* __restrict__ AH, const __nv_bfloat16* __restrict__ AL,
    const float* __restrict__ W, const float* __restrict__ bias,
    float* __restrict__ C,                      // fp32 out (GEMM2)
    __nv_bfloat16* __restrict__ CH,             // bf16 hi out (GEMM1)
    __nv_bfloat16* __restrict__ CL,             // bf16 lo out (GEMM1)
    int n, int doStats, int numTiles)
{
    extern __shared__ __nv_bfloat16 sb[];
    __nv_bfloat16* Ah = sb;                    // [64][PAD]
    __nv_bfloat16* Al = sb + BR * PAD;
    __nv_bfloat16* Wh = sb + 2 * BR * PAD;     // [128][PAD] transposed [n][k]
    __nv_bfloat16* Wl = Wh + D * PAD;

    int t = threadIdx.x;
    int warp = t >> 5, lane = t & 31;

    for (int i = t; i < D * D; i += 256) {
        int k = i >> 7, nn = i & 127;
        float w = W[i];
        __nv_bfloat16 hh = __float2bfloat16(w);
        float rest = w - __bfloat162float(hh);
        Wh[nn * PAD + k] = hh;
        Wl[nn * PAD + k] = __float2bfloat16(rest);
    }

    int rowSub = (warp & 1) * 32;
    int colQ   = (warp >> 1) * 32;
    int cb     = (lane & 3) * 2;
    int quad   = lane >> 3, lrow = lane & 7;
    int l16    = lane & 15;

    float bias_r[4][2];
#pragma unroll
    for (int nn = 0; nn < 4; nn++) {
        bias_r[nn][0] = bias[colQ + nn * 8 + cb];
        bias_r[nn][1] = bias[colQ + nn * 8 + cb + 1];
    }

    float ss[8], sq[8];
#pragma unroll
    for (int i = 0; i < 8; i++) { ss[i] = 0.f; sq[i] = 0.f; }

    int aRowOff = (quad & 1) * 8 + lrow;
    int aColOff = (quad >> 1) * 8;
    int bRowOff = l16 & 7;
    int bColOff = (l16 >> 3) * 8;

    __syncthreads();

    for (int tile = blockIdx.x; tile < numTiles; tile += gridDim.x) {
        int row0 = tile * BR;

#pragma unroll
        for (int j = 0; j < 8; j++) {
            int idx = t + j * 256;
            int half = idx >> 10;             // 0=hi 1=lo
            int r = (idx & 1023) >> 4;
            int ck = idx & 15;
            int gr = row0 + r;
            __nv_bfloat16* dst = (half ? Al : Ah) + r * PAD + ck * 8;
            if (gr < n) {
                const __nv_bfloat16* src =
                    (half ? AL : AH) + (size_t)gr * D + ck * 8;
                unsigned du = (unsigned)__cvta_generic_to_shared(dst);
                asm volatile("cp.async.cg.shared.global [%0], [%1], 16;"
                             :: "r"(du), "l"(src));
            } else {
                *(float4*)dst = make_float4(0.f, 0.f, 0.f, 0.f);
            }
        }
        asm volatile("cp.async.commit_group;");
        asm volatile("cp.async.wait_group 0;");
        __syncthreads();

        float acc[2][4][4];
#pragma unroll
        for (int rs = 0; rs < 2; rs++)
#pragma unroll
            for (int nn = 0; nn < 4; nn++)
#pragma unroll
                for (int u = 0; u < 4; u++) acc[rs][nn][u] = 0.f;

#pragma unroll
        for (int k0 = 0; k0 < D; k0 += 16) {
            unsigned ah[2][4], al[2][4];
#pragma unroll
            for (int rs = 0; rs < 2; rs++) {
                const __nv_bfloat16* pa =
                    Ah + (rowSub + rs * 16 + aRowOff) * PAD + k0 + aColOff;
                unsigned sa = (unsigned)__cvta_generic_to_shared(pa);
                asm volatile("ldmatrix.sync.aligned.m8n8.x4.shared.b16 "
                             "{%0,%1,%2,%3}, [%4];"
                             : "=r"(ah[rs][0]), "=r"(ah[rs][1]),
                               "=r"(ah[rs][2]), "=r"(ah[rs][3]) : "r"(sa));
                const __nv_bfloat16* pl =
                    Al + (rowSub + rs * 16 + aRowOff) * PAD + k0 + aColOff;
                unsigned sl = (unsigned)__cvta_generic_to_shared(pl);
                asm volatile("ldmatrix.sync.aligned.m8n8.x4.shared.b16 "
                             "{%0,%1,%2,%3}, [%4];"
                             : "=r"(al[rs][0]), "=r"(al[rs][1]),
                               "=r"(al[rs][2]), "=r"(al[rs][3]) : "r"(sl));
            }
            unsigned bh[4][2], bl[4][2];
#pragma unroll
            for (int nn = 0; nn < 4; nn++) {
                const __nv_bfloat16* pb =
                    Wh + (colQ + nn * 8 + bRowOff) * PAD + k0 + bColOff;
                unsigned sbh = (unsigned)__cvta_generic_to_shared(pb);
                asm volatile("ldmatrix.sync.aligned.m8n8.x2.shared.b16 "
                             "{%0,%1}, [%2];"
                             : "=r"(bh[nn][0]), "=r"(bh[nn][1]) : "r"(sbh));
                const __nv_bfloat16* pbl =
                    Wl + (colQ + nn * 8 + bRowOff) * PAD + k0 + bColOff;
                unsigned sbl = (unsigned)__cvta_generic_to_shared(pbl);
                asm volatile("ldmatrix.sync.aligned.m8n8.x2.shared.b16 "
                             "{%0,%1}, [%2];"
                             : "=r"(bl[nn][0]), "=r"(bl[nn][1]) : "r"(sbl));
            }
#pragma unroll
            for (int rs = 0; rs < 2; rs++)
#pragma unroll
                for (int nn = 0; nn < 4; nn++) {
                    mma16816(acc[rs][nn], ah[rs], bh[nn]);
                    mma16816(acc[rs][nn], ah[rs], bl[nn]);
                    mma16816(acc[rs][nn], al[rs], bh[nn]);
                }
        }

#pragma unroll
        for (int rs = 0; rs < 2; rs++) {
            int rA = row0 + rowSub + rs * 16 + (lane >> 2);
            int rB = rA + 8;
#pragma unroll
            for (int nn = 0; nn < 4; nn++) {
                int c = colQ + nn * 8 + cb;
#pragma unroll
                for (int hb = 0; hb < 2; hb++) {
                    int rr = hb ? rB : rA;
                    if (rr >= n) continue;
                    float o0 = fmaxf(acc[rs][nn][hb * 2 + 0] + bias_r[nn][0], 0.f);
                    float o1 = fmaxf(acc[rs][nn][hb * 2 + 1] + bias_r[nn][1], 0.f);
                    if (C) {
                        *(float2*)(C + (size_t)rr * D + c) = make_float2(o0, o1);
                    } else {
                        __nv_bfloat16 h0 = __float2bfloat16(o0);
                        __nv_bfloat16 h1 = __float2bfloat16(o1);
                        unsigned hp = __bfloat16_as_ushort(h0) |
                                      ((unsigned)__bfloat16_as_ushort(h1) << 16);
                        float r0f = o0 - __bfloat162float(h0);
                        float r1f = o1 - __bfloat162float(h1);
                        unsigned lp = __bfloat16_as_ushort(__float2bfloat16(r0f)) |
                                      ((unsigned)__bfloat16_as_ushort(__float2bfloat16(r1f)) << 16);
                        *(unsigned*)(CH + (size_t)rr * D + c) = hp;
                        *(unsigned*)(CL + (size_t)rr * D + c) = lp;
                    }
                    if (doStats) {
                        ss[nn * 2 + 0] += o0; sq[nn * 2 + 0] += o0 * o0;
                        ss[nn * 2 + 1] += o1; sq[nn * 2 + 1] += o1 * o1;
                    }
                }
            }
        }
        __syncthreads();
    }

    if (doStats) {
#pragma unroll
        for (int i = 0; i < 8; i++) {
#pragma unroll
            for (int m = 4; m <= 16; m <<= 1) {
                ss[i] += __shfl_xor_sync(0xFFFFFFFFu, ss[i], m);
                sq[i] += __shfl_xor_sync(0xFFFFFFFFu, sq[i], m);
            }
        }
        if (lane < 4) {
#pragma unroll
            for (int nn = 0; nn < 4; nn++) {
                int c = colQ + nn * 8 + lane * 2;
                atomicAdd(&g_colsum[c + 0], ss[nn * 2 + 0]);
                atomicAdd(&g_colsum[c + 1], ss[nn * 2 + 1]);
                atomicAdd(&g_colsq[c + 0], sq[nn * 2 + 0]);
                atomicAdd(&g_colsq[c + 1], sq[nn * 2 + 1]);
            }
        }
    }
}

// one block per graph; applies BN affine on the fly; no atomics
__global__ void seg_max_kernel(float* __restrict__ out, int n)
{
    int g = blockIdx.x;
    int col = threadIdx.x;      // 0..127
    int s = g_gstart[g], e = g_gstart[g + 1];
    float sc0 = g_bnsc[0][col], bt0 = g_bnbt[0][col];
    float sc1 = g_bnsc[1][col], bt1 = g_bnbt[1][col];
    float sc2 = g_bnsc[2][col], bt2 = g_bnbt[2][col];
    float m0 = -3.402823466e+38f, m1 = m0, m2 = m0;
    for (int node = s; node < e; node++) {
        m0 = fmaxf(m0, sc0 * g_m[0][(size_t)node * D + col] + bt0);
        m1 = fmaxf(m1, sc1 * g_m[1][(size_t)node * D + col] + bt1);
        m2 = fmaxf(m2, sc2 * g_m[2][(size_t)node * D + col] + bt2);
    }
    out[g * (LAYERS * D) + col] = m0;
    out[g * (LAYERS * D) + D + col] = m1;
    out[g * (LAYERS * D) + 2 * D + col] = m2;
}

// ---------------- launch -----------------------------------------------------

extern "C" void kernel_launch(void* const* d_in, const int* in_sizes, int n_in,
                              void* d_out, int out_size)
{
    const float* x     = (const float*)d_in[0];
    const int*   ei    = (const int*)d_in[1];
    const int*   batch = (const int*)d_in[2];
    const float* W1    = (const float*)d_in[3];
    const float* b1    = (const float*)d_in[4];
    const float* W2    = (const float*)d_in[5];
    const float* b2    = (const float*)d_in[6];
    const float* gamma = (const float*)d_in[7];
    const float* beta  = (const float*)d_in[8];
    float* out = (float*)d_out;

    int n  = in_sizes[0] / D;
    int ne = in_sizes[1] / 2;
    int G  = out_size / (LAYERS * D);
    float invN = 1.0f / (float)n;

    __nv_bfloat16 *p_aggH, *p_aggL, *p_m1H, *p_m1L;
    float *p_m;
    cudaGetSymbolAddress((void**)&p_aggH, g_aggH);
    cudaGetSymbolAddress((void**)&p_aggL, g_aggL);
    cudaGetSymbolAddress((void**)&p_m1H,  g_m1H);
    cudaGetSymbolAddress((void**)&p_m1L,  g_m1L);
    cudaGetSymbolAddress((void**)&p_m,    g_m);

    int smem = (2 * BR * PAD + 2 * D * PAD) * (int)sizeof(__nv_bfloat16);
    cudaFuncSetAttribute(gemm_relu_tc_kernel,
                         cudaFuncAttributeMaxDynamicSharedMemorySize, smem);

    int numTiles = (n + BR - 1) / BR;
    int gemmGrid = 296;
    int nc = (n + CHUNK - 1) / CHUNK;

    // CSR build (once; reused across layers)
    csr_zero_kernel<<<(n + 255) / 256, 256>>>(n);
    csr_hist_kernel<<<(ne + 255) / 256, 256>>>(ei, ne);
    chunk_sum_kernel<<<nc, 256>>>(n);
    chunk_scan_kernel<<<1, 128>>>(nc, n);
    fill_rowptr_kernel<<<nc, CHUNK>>>(n);
    csr_bucket_kernel<<<(ne + 255) / 256, 256>>>(ei, ne);
    gstart_kernel<<<(n + 255) / 256, 256>>>(batch, n, G);

    int gatherBlocks = (n * 32 + 255) / 256;
    for (int i = 0; i < LAYERS; i++) {
        gather_kernel<<<gatherBlocks, 256>>>(x, i, n);
        gemm_relu_tc_kernel<<<gemmGrid, 256, smem>>>(
            p_aggH, p_aggL, W1 + i * D * D, b1 + i * D,
            nullptr, p_m1H, p_m1L, n, 0, numTiles);
        gemm_relu_tc_kernel<<<gemmGrid, 256, smem>>>(
            p_m1H, p_m1L, W2 + i * D * D, b2 + i * D,
            p_m + (size_t)i * MAXN * D, nullptr, nullptr, n, 1, numTiles);
        bn_stats_kernel<<<1, D>>>(i, gamma + i * D, beta + i * D, invN);
    }

    seg_max_kernel<<<G, D>>>(out, n);
}

// round 11
// speedup vs baseline: 14.9361x; 1.0946x over previous
#include <cuda_runtime.h>
#include <cuda_bf16.h>
#include <cstdint>

#define D 128
#define LAYERS 3
#define MAXN 100000
#define MAXE 1600000
#define MAXG 2048
#define TR 128         // fused GEMM rows per tile
#define PAD 136        // bf16 row stride (272B) -> conflict-free ldmatrix
#define BN_EPS 1e-5f
#define CHUNK 1024

// ---------------- scratch ----------------------------------------------------
__device__ float         g_m[LAYERS][MAXN * D];   // pre-BN layer outputs
__device__ __nv_bfloat16 g_aggH[MAXN * D];
__device__ __nv_bfloat16 g_aggL[MAXN * D];
__device__ float         g_colsum[D];
__device__ float         g_colsq[D];
__device__ float         g_bnsc[LAYERS][D];
__device__ float         g_bnbt[LAYERS][D];
__device__ int           g_deg[MAXN];
__device__ int           g_fill[MAXN];
__device__ int           g_rowPtr[MAXN + 1];
__device__ int           g_chunkSum[(MAXN + CHUNK - 1) / CHUNK];
__device__ int           g_chunkOff[(MAXN + CHUNK - 1) / CHUNK];
__device__ int           g_csrSrc[MAXE];
__device__ int           g_gstart[MAXG + 1];

// ---------------- CSR build --------------------------------------------------

__global__ void csr_zero_kernel(int n)
{
    int i = blockIdx.x * blockDim.x + threadIdx.x;
    if (i < n) { g_deg[i] = 0; g_fill[i] = 0; }
}

__global__ void csr_hist_kernel(const int* __restrict__ ei, int ne)
{
    int e = blockIdx.x * blockDim.x + threadIdx.x;
    if (e < ne) atomicAdd(&g_deg[ei[ne + e]], 1);
}

__global__ void chunk_sum_kernel(int n)
{
    __shared__ int sh[256];
    int base = blockIdx.x * CHUNK;
    int s = 0;
    for (int j = threadIdx.x; j < CHUNK; j += 256) {
        int i = base + j;
        s += (i < n) ? g_deg[i] : 0;
    }
    sh[threadIdx.x] = s; __syncthreads();
    for (int m = 128; m > 0; m >>= 1) {
        if (threadIdx.x < m) sh[threadIdx.x] += sh[threadIdx.x + m];
        __syncthreads();
    }
    if (threadIdx.x == 0) g_chunkSum[blockIdx.x] = sh[0];
}

__global__ void chunk_scan_kernel(int nc, int n)
{
    __shared__ int sh[128];
    int t = threadIdx.x;
    int v = (t < nc) ? g_chunkSum[t] : 0;
    sh[t] = v; __syncthreads();
    for (int off = 1; off < 128; off <<= 1) {
        int x = 0;
        if (t >= off) x = sh[t - off];
        __syncthreads();
        sh[t] += x;
        __syncthreads();
    }
    if (t < nc) g_chunkOff[t] = sh[t] - v;
    if (t == 127) g_rowPtr[n] = sh[127];
}

__global__ void fill_rowptr_kernel(int n)
{
    __shared__ int sh[CHUNK];
    int t = threadIdx.x;
    int i = blockIdx.x * CHUNK + t;
    int v = (i < n) ? g_deg[i] : 0;
    sh[t] = v; __syncthreads();
    for (int off = 1; off < CHUNK; off <<= 1) {
        int x = 0;
        if (t >= off) x = sh[t - off];
        __syncthreads();
        sh[t] += x;
        __syncthreads();
    }
    if (i < n) g_rowPtr[i] = g_chunkOff[blockIdx.x] + sh[t] - v;
}

__global__ void csr_bucket_kernel(const int* __restrict__ ei, int ne)
{
    int e = blockIdx.x * blockDim.x + threadIdx.x;
    if (e >= ne) return;
    int s = ei[e], d = ei[ne + e];
    int pos = g_rowPtr[d] + atomicAdd(&g_fill[d], 1);
    g_csrSrc[pos] = s;
}

__global__ void gstart_kernel(const int* __restrict__ batch, int n, int G)
{
    int i = blockIdx.x * blockDim.x + threadIdx.x;
    if (i >= n) return;
    int b = batch[i];
    int prev = (i == 0) ? -1 : batch[i - 1];
    for (int g = prev + 1; g <= b; g++) g_gstart[g] = i;
    if (i == n - 1)
        for (int g = b + 1; g <= G; g++) g_gstart[g] = n;
}

// ---------------- bf16 split helpers -----------------------------------------
__device__ __forceinline__ uint2 split_hi(float4 v)
{
    unsigned u0 = __bfloat16_as_ushort(__float2bfloat16(v.x));
    unsigned u1 = __bfloat16_as_ushort(__float2bfloat16(v.y));
    unsigned u2 = __bfloat16_as_ushort(__float2bfloat16(v.z));
    unsigned u3 = __bfloat16_as_ushort(__float2bfloat16(v.w));
    return make_uint2(u0 | (u1 << 16), u2 | (u3 << 16));
}
__device__ __forceinline__ uint2 split_lo(float4 v)
{
    float r0 = v.x - __bfloat162float(__float2bfloat16(v.x));
    float r1 = v.y - __bfloat162float(__float2bfloat16(v.y));
    float r2 = v.z - __bfloat162float(__float2bfloat16(v.z));
    float r3 = v.w - __bfloat162float(__float2bfloat16(v.w));
    unsigned u0 = __bfloat16_as_ushort(__float2bfloat16(r0));
    unsigned u1 = __bfloat16_as_ushort(__float2bfloat16(r1));
    unsigned u2 = __bfloat16_as_ushort(__float2bfloat16(r2));
    unsigned u3 = __bfloat16_as_ushort(__float2bfloat16(r3));
    return make_uint2(u0 | (u1 << 16), u2 | (u3 << 16));
}

// ---------------- gather: BN affine folded in, bf16 hi/lo out ----------------
__global__ void gather_kernel(const float* __restrict__ x, int layer, int n)
{
    int t = blockIdx.x * blockDim.x + threadIdx.x;
    if (blockIdx.x == 0 && threadIdx.x < D) {
        g_colsum[threadIdx.x] = 0.f;
        g_colsq[threadIdx.x] = 0.f;
    }
    int w = t >> 5;
    if (w >= n) return;
    int lane = t & 31;
    const float* h = (layer == 0) ? x : g_m[layer - 1];
    int start = g_rowPtr[w], end = g_rowPtr[w + 1];
    float4 acc = *(const float4*)(h + (size_t)w * D + lane * 4);
    for (int base = start; base < end; base += 32) {
        int idx = base + lane;
        int sv = (idx < end) ? g_csrSrc[idx] : 0;
        int cnt = min(32, end - base);
        for (int j = 0; j < cnt; j++) {
            int s = __shfl_sync(0xFFFFFFFFu, sv, j);
            float4 vv = *(const float4*)(h + (size_t)s * D + lane * 4);
            acc.x += vv.x; acc.y += vv.y; acc.z += vv.z; acc.w += vv.w;
        }
    }
    if (layer > 0) {
        float4 sc = *(const float4*)(&g_bnsc[layer - 1][lane * 4]);
        float4 bt = *(const float4*)(&g_bnbt[layer - 1][lane * 4]);
        float cnt1 = (float)(end - start + 1);
        acc.x = sc.x * acc.x + cnt1 * bt.x;
        acc.y = sc.y * acc.y + cnt1 * bt.y;
        acc.z = sc.z * acc.z + cnt1 * bt.z;
        acc.w = sc.w * acc.w + cnt1 * bt.w;
    }
    *(uint2*)(g_aggH + (size_t)w * D + lane * 4) = split_hi(acc);
    *(uint2*)(g_aggL + (size_t)w * D + lane * 4) = split_lo(acc);
}

__global__ void bn_stats_kernel(int layer, const float* __restrict__ gamma,
                                const float* __restrict__ beta, float invN)
{
    int c = threadIdx.x;
    float mean = g_colsum[c] * invN;
    float var = g_colsq[c] * invN - mean * mean;
    float sc = gamma[c] * rsqrtf(var + BN_EPS);
    g_bnsc[layer][c] = sc;
    g_bnbt[layer][c] = beta[c] - sc * mean;
}

// ---- fused MLP: m = relu(relu(A@W1+b1)@W2+b2), bf16x3 tensor cores ----------
__device__ __forceinline__ void mma16816(float* d, const unsigned* a,
                                         const unsigned* b)
{
    asm volatile(
        "mma.sync.aligned.m16n8k16.row.col.f32.bf16.bf16.f32 "
        "{%0,%1,%2,%3}, {%4,%5,%6,%7}, {%8,%9}, {%0,%1,%2,%3};"
        : "+f"(d[0]), "+f"(d[1]), "+f"(d[2]), "+f"(d[3])
        : "r"(a[0]), "r"(a[1]), "r"(a[2]), "r"(a[3]), "r"(b[0]), "r"(b[1]));
}

// warp computes acc[2][4][4] = 32x32 tile of Asrc(hi/lo) @ Bsrc(hi/lo, [n][k])
__device__ __forceinline__ void warp_gemm_128(
    const __nv_bfloat16* Ah, const __nv_bfloat16* Al,
    const __nv_bfloat16* Bh, const __nv_bfloat16* Bl,
    int rowSub, int colQ, int aRowOff, int aColOff, int bRowOff, int bColOff,
    float acc[2][4][4])
{
#pragma unroll
    for (int rs = 0; rs < 2; rs++)
#pragma unroll
        for (int nn = 0; nn < 4; nn++)
#pragma unroll
            for (int u = 0; u < 4; u++) acc[rs][nn][u] = 0.f;

#pragma unroll
    for (int k0 = 0; k0 < D; k0 += 16) {
        unsigned ah[2][4], al[2][4];
#pragma unroll
        for (int rs = 0; rs < 2; rs++) {
            const __nv_bfloat16* pa =
                Ah + (rowSub + rs * 16 + aRowOff) * PAD + k0 + aColOff;
            unsigned sa = (unsigned)__cvta_generic_to_shared(pa);
            asm volatile("ldmatrix.sync.aligned.m8n8.x4.shared.b16 "
                         "{%0,%1,%2,%3}, [%4];"
                         : "=r"(ah[rs][0]), "=r"(ah[rs][1]),
                           "=r"(ah[rs][2]), "=r"(ah[rs][3]) : "r"(sa));
            const __nv_bfloat16* pl =
                Al + (rowSub + rs * 16 + aRowOff) * PAD + k0 + aColOff;
            unsigned sl = (unsigned)__cvta_generic_to_shared(pl);
            asm volatile("ldmatrix.sync.aligned.m8n8.x4.shared.b16 "
                         "{%0,%1,%2,%3}, [%4];"
                         : "=r"(al[rs][0]), "=r"(al[rs][1]),
                           "=r"(al[rs][2]), "=r"(al[rs][3]) : "r"(sl));
        }
        unsigned bh[4][2], bl[4][2];
#pragma unroll
        for (int nn = 0; nn < 4; nn++) {
            const __nv_bfloat16* pb =
                Bh + (colQ + nn * 8 + bRowOff) * PAD + k0 + bColOff;
            unsigned sbh = (unsigned)__cvta_generic_to_shared(pb);
            asm volatile("ldmatrix.sync.aligned.m8n8.x2.shared.b16 "
                         "{%0,%1}, [%2];"
                         : "=r"(bh[nn][0]), "=r"(bh[nn][1]) : "r"(sbh));
            const __nv_bfloat16* pbl =
                Bl + (colQ + nn * 8 + bRowOff) * PAD + k0 + bColOff;
            unsigned sbl = (unsigned)__cvta_generic_to_shared(pbl);
            asm volatile("ldmatrix.sync.aligned.m8n8.x2.shared.b16 "
                         "{%0,%1}, [%2];"
                         : "=r"(bl[nn][0]), "=r"(bl[nn][1]) : "r"(sbl));
        }
#pragma unroll
        for (int rs = 0; rs < 2; rs++)
#pragma unroll
            for (int nn = 0; nn < 4; nn++) {
                mma16816(acc[rs][nn], ah[rs], bh[nn]);
                mma16816(acc[rs][nn], ah[rs], bl[nn]);
                mma16816(acc[rs][nn], al[rs], bh[nn]);
            }
    }
}

__global__ __launch_bounds__(512) void mlp_fused_kernel(
    const __nv_bfloat16* __restrict__ AH, const __nv_bfloat16* __restrict__ AL,
    const float* __restrict__ W1, const float* __restrict__ b1,
    const float* __restrict__ W2, const float* __restrict__ b2,
    float* __restrict__ C, int n, int numTiles)
{
    extern __shared__ __nv_bfloat16 sb[];
    __nv_bfloat16* Ah  = sb;                    // [128][PAD]; reused as M1 hi
    __nv_bfloat16* Al  = Ah + TR * PAD;         // [128][PAD]; reused as M1 lo
    __nv_bfloat16* W1h = Al + TR * PAD;         // [128][PAD] transposed [n][k]
    __nv_bfloat16* W1l = W1h + D * PAD;
    __nv_bfloat16* W2h = W1l + D * PAD;
    __nv_bfloat16* W2l = W2h + D * PAD;

    int t = threadIdx.x;
    int warp = t >> 5, lane = t & 31;

    // load + split + transpose both weights (once per block)
    for (int i = t; i < D * D; i += 512) {
        int k = i >> 7, nn = i & 127;
        float w = W1[i];
        __nv_bfloat16 hh = __float2bfloat16(w);
        W1h[nn * PAD + k] = hh;
        W1l[nn * PAD + k] = __float2bfloat16(w - __bfloat162float(hh));
        float w2 = W2[i];
        __nv_bfloat16 hh2 = __float2bfloat16(w2);
        W2h[nn * PAD + k] = hh2;
        W2l[nn * PAD + k] = __float2bfloat16(w2 - __bfloat162float(hh2));
    }

    int rowSub = (warp & 3) * 32;
    int colQ   = (warp >> 2) * 32;
    int cb     = (lane & 3) * 2;
    int quad   = lane >> 3, lrow = lane & 7;
    int l16    = lane & 15;
    int aRowOff = (quad & 1) * 8 + lrow;
    int aColOff = (quad >> 1) * 8;
    int bRowOff = l16 & 7;
    int bColOff = (l16 >> 3) * 8;

    float b1_r[4][2], b2_r[4][2];
#pragma unroll
    for (int nn = 0; nn < 4; nn++) {
        b1_r[nn][0] = b1[colQ + nn * 8 + cb];
        b1_r[nn][1] = b1[colQ + nn * 8 + cb + 1];
        b2_r[nn][0] = b2[colQ + nn * 8 + cb];
        b2_r[nn][1] = b2[colQ + nn * 8 + cb + 1];
    }

    float ss[8], sq[8];
#pragma unroll
    for (int i = 0; i < 8; i++) { ss[i] = 0.f; sq[i] = 0.f; }

    __syncthreads();

    for (int tile = blockIdx.x; tile < numTiles; tile += gridDim.x) {
        int row0 = tile * TR;

        // A fill: 128 rows x 16 chunks x 2 halves = 4096 x 16B via cp.async
#pragma unroll
        for (int j = 0; j < 8; j++) {
            int idx = t + j * 512;
            int half = idx >> 11;
            int r = (idx & 2047) >> 4;
            int ck = idx & 15;
            int gr = row0 + r;
            __nv_bfloat16* dst = (half ? Al : Ah) + r * PAD + ck * 8;
            if (gr < n) {
                const __nv_bfloat16* src =
                    (half ? AL : AH) + (size_t)gr * D + ck * 8;
                unsigned du = (unsigned)__cvta_generic_to_shared(dst);
                asm volatile("cp.async.cg.shared.global [%0], [%1], 16;"
                             :: "r"(du), "l"(src));
            } else {
                *(float4*)dst = make_float4(0.f, 0.f, 0.f, 0.f);
            }
        }
        asm volatile("cp.async.commit_group;");
        asm volatile("cp.async.wait_group 0;");
        __syncthreads();

        // GEMM1: M1 = relu(A @ W1 + b1)
        float acc[2][4][4];
        warp_gemm_128(Ah, Al, W1h, W1l, rowSub, colQ,
                      aRowOff, aColOff, bRowOff, bColOff, acc);
        __syncthreads();   // all A reads done; safe to overwrite with M1

#pragma unroll
        for (int rs = 0; rs < 2; rs++) {
            int rA = rowSub + rs * 16 + (lane >> 2);
#pragma unroll
            for (int nn = 0; nn < 4; nn++) {
                int c = colQ + nn * 8 + cb;
#pragma unroll
                for (int hb = 0; hb < 2; hb++) {
                    int rr = rA + hb * 8;
                    float o0 = fmaxf(acc[rs][nn][hb * 2 + 0] + b1_r[nn][0], 0.f);
                    float o1 = fmaxf(acc[rs][nn][hb * 2 + 1] + b1_r[nn][1], 0.f);
                    __nv_bfloat16 h0 = __float2bfloat16(o0);
                    __nv_bfloat16 h1 = __float2bfloat16(o1);
                    unsigned hp = __bfloat16_as_ushort(h0) |
                                  ((unsigned)__bfloat16_as_ushort(h1) << 16);
                    unsigned lp = __bfloat16_as_ushort(
                                      __float2bfloat16(o0 - __bfloat162float(h0))) |
                                  ((unsigned)__bfloat16_as_ushort(
                                      __float2bfloat16(o1 - __bfloat162float(h1))) << 16);
                    *(unsigned*)(Ah + rr * PAD + c) = hp;
                    *(unsigned*)(Al + rr * PAD + c) = lp;
                }
            }
        }
        __syncthreads();   // M1 visible to all warps

        // GEMM2: m = relu(M1 @ W2 + b2) -> global + stats
        warp_gemm_128(Ah, Al, W2h, W2l, rowSub, colQ,
                      aRowOff, aColOff, bRowOff, bColOff, acc);

#pragma unroll
        for (int rs = 0; rs < 2; rs++) {
            int rA = row0 + rowSub + rs * 16 + (lane >> 2);
#pragma unroll
            for (int nn = 0; nn < 4; nn++) {
                int c = colQ + nn * 8 + cb;
#pragma unroll
                for (int hb = 0; hb < 2; hb++) {
                    int rr = rA + hb * 8;
                    if (rr >= n) continue;
                    float o0 = fmaxf(acc[rs][nn][hb * 2 + 0] + b2_r[nn][0], 0.f);
                    float o1 = fmaxf(acc[rs][nn][hb * 2 + 1] + b2_r[nn][1], 0.f);
                    *(float2*)(C + (size_t)rr * D + c) = make_float2(o0, o1);
                    ss[nn * 2 + 0] += o0; sq[nn * 2 + 0] += o0 * o0;
                    ss[nn * 2 + 1] += o1; sq[nn * 2 + 1] += o1 * o1;
                }
            }
        }
        __syncthreads();   // M1 reads done before next tile overwrites
    }

    // flush BN stats
#pragma unroll
    for (int i = 0; i < 8; i++) {
#pragma unroll
        for (int m = 4; m <= 16; m <<= 1) {
            ss[i] += __shfl_xor_sync(0xFFFFFFFFu, ss[i], m);
            sq[i] += __shfl_xor_sync(0xFFFFFFFFu, sq[i], m);
        }
    }
    if (lane < 4) {
#pragma unroll
        for (int nn = 0; nn < 4; nn++) {
            int c = colQ + nn * 8 + lane * 2;
            atomicAdd(&g_colsum[c + 0], ss[nn * 2 + 0]);
            atomicAdd(&g_colsum[c + 1], ss[nn * 2 + 1]);
            atomicAdd(&g_colsq[c + 0], sq[nn * 2 + 0]);
            atomicAdd(&g_colsq[c + 1], sq[nn * 2 + 1]);
        }
    }
}

// one block per graph; applies BN affine on the fly; no atomics
__global__ void seg_max_kernel(float* __restrict__ out, int n)
{
    int g = blockIdx.x;
    int col = threadIdx.x;
    int s = g_gstart[g], e = g_gstart[g + 1];
    float sc0 = g_bnsc[0][col], bt0 = g_bnbt[0][col];
    float sc1 = g_bnsc[1][col], bt1 = g_bnbt[1][col];
    float sc2 = g_bnsc[2][col], bt2 = g_bnbt[2][col];
    float m0 = -3.402823466e+38f, m1 = m0, m2 = m0;
    for (int node = s; node < e; node++) {
        m0 = fmaxf(m0, sc0 * g_m[0][(size_t)node * D + col] + bt0);
        m1 = fmaxf(m1, sc1 * g_m[1][(size_t)node * D + col] + bt1);
        m2 = fmaxf(m2, sc2 * g_m[2][(size_t)node * D + col] + bt2);
    }
    out[g * (LAYERS * D) + col] = m0;
    out[g * (LAYERS * D) + D + col] = m1;
    out[g * (LAYERS * D) + 2 * D + col] = m2;
}

// ---------------- launch -----------------------------------------------------

extern "C" void kernel_launch(void* const* d_in, const int* in_sizes, int n_in,
                              void* d_out, int out_size)
{
    const float* x     = (const float*)d_in[0];
    const int*   ei    = (const int*)d_in[1];
    const int*   batch = (const int*)d_in[2];
    const float* W1    = (const float*)d_in[3];
    const float* b1    = (const float*)d_in[4];
    const float* W2    = (const float*)d_in[5];
    const float* b2    = (const float*)d_in[6];
    const float* gamma = (const float*)d_in[7];
    const float* beta  = (const float*)d_in[8];
    float* out = (float*)d_out;

    int n  = in_sizes[0] / D;
    int ne = in_sizes[1] / 2;
    int G  = out_size / (LAYERS * D);
    float invN = 1.0f / (float)n;

    __nv_bfloat16 *p_aggH, *p_aggL;
    float *p_m;
    cudaGetSymbolAddress((void**)&p_aggH, g_aggH);
    cudaGetSymbolAddress((void**)&p_aggL, g_aggL);
    cudaGetSymbolAddress((void**)&p_m,    g_m);

    int smem = (2 * TR * PAD + 4 * D * PAD) * (int)sizeof(__nv_bfloat16); // 208896
    cudaFuncSetAttribute(mlp_fused_kernel,
                         cudaFuncAttributeMaxDynamicSharedMemorySize, smem);

    int numTiles = (n + TR - 1) / TR;
    int nc = (n + CHUNK - 1) / CHUNK;

    // CSR build (once; reused across layers)
    csr_zero_kernel<<<(n + 255) / 256, 256>>>(n);
    csr_hist_kernel<<<(ne + 255) / 256, 256>>>(ei, ne);
    chunk_sum_kernel<<<nc, 256>>>(n);
    chunk_scan_kernel<<<1, 128>>>(nc, n);
    fill_rowptr_kernel<<<nc, CHUNK>>>(n);
    csr_bucket_kernel<<<(ne + 255) / 256, 256>>>(ei, ne);
    gstart_kernel<<<(n + 255) / 256, 256>>>(batch, n, G);

    int gatherBlocks = (n * 32 + 255) / 256;
    for (int i = 0; i < LAYERS; i++) {
        gather_kernel<<<gatherBlocks, 256>>>(x, i, n);
        mlp_fused_kernel<<<148, 512, smem>>>(
            p_aggH, p_aggL, W1 + i * D * D, b1 + i * D,
            W2 + i * D * D, b2 + i * D,
            p_m + (size_t)i * MAXN * D, n, numTiles);
        bn_stats_kernel<<<1, D>>>(i, gamma + i * D, beta + i * D, invN);
    }

    seg_max_kernel<<<G, D>>>(out, n);
}